// round 10
// baseline (speedup 1.0000x reference)
#include <cuda_runtime.h>
#include <cuda_fp16.h>
#include <cstdint>
#include <math.h>

#define N_NODES  50000
#define N_EDGES  800000
#define N_GRAPHS 64
#define SCAN_B   1024
#define NB_SCAN  ((N_NODES + SCAN_B - 1) / SCAN_B)   // 49
#define PA 40                     // smem pitch in halves
#define PLANE_A (128 * PA)        // A plane halves
#define PLANE_B (256 * PA)        // B plane halves
#define SS (2 * PLANE_A + 2 * PLANE_B)          // halves per stage
#define SMEM_BYTES (2 * SS * 2)                 // 2 stages -> 122880 bytes

// ---------------- scratch (device globals; no allocation allowed) ----------
__device__ __align__(16) __half g_h0hi[N_NODES * 256];
__device__ __align__(16) __half g_h0lo[N_NODES * 256];
__device__ __align__(16) __half g_a1hi[N_NODES * 256];
__device__ __align__(16) __half g_a1lo[N_NODES * 256];
__device__ __align__(16) __half g_h1hi[N_NODES * 256];
__device__ __align__(16) __half g_h1lo[N_NODES * 256];
__device__ __align__(16) float  g_pq[N_NODES * 256];
__device__ __align__(16) __half g_W1hi[256 * 512];
__device__ __align__(16) __half g_W1lo[256 * 512];
__device__ __align__(16) __half g_W2hi[256 * 256];
__device__ __align__(16) __half g_W2lo[256 * 256];
__device__ float g_dinv[N_NODES];
__device__ int   g_cnt[N_NODES];
__device__ int   g_rowstart[N_NODES];
__device__ int   g_cursor[N_NODES];
__device__ int   g_inlist[N_EDGES];
__device__ float g_gsum[N_GRAPHS * 128];
__device__ int   g_gcnt[N_GRAPHS];
__device__ int   g_bsums[64];

__device__ int     g_ei64;
__device__ int     g_b64;
__device__ __half* g_hp[10];  // 0:h0hi 1:h0lo 2:a1hi 3:a1lo 4:h1hi 5:h1lo 6:W1hi 7:W1lo 8:W2hi 9:W2lo

__device__ __forceinline__ int ld_idx(const void* p, long long i, int is64) {
    return is64 ? (int)((const long long*)p)[i] : ((const int*)p)[i];
}

__device__ __forceinline__ void split_f32(float v, __half& hi, __half& lo) {
    hi = __float2half_rn(v);
    lo = __float2half_rn(v - __half2float(hi));
}

__device__ __forceinline__ unsigned smem_u32(const void* p) {
    return (unsigned)__cvta_generic_to_shared(p);
}

__device__ __forceinline__ void cp16(unsigned dst, const void* src) {
    asm volatile("cp.async.cg.shared.global [%0], [%1], 16;\n" :: "r"(dst), "l"(src));
}

// ---------------- setup: dtype detect + pointers + zero + weight split ------
__global__ void k_setup(const int* ei_w, const int* b_w,
                        const float* __restrict__ Wl1, const float* __restrict__ Wr1,
                        const float* __restrict__ Wl2, const float* __restrict__ Wr2) {
    int i = blockIdx.x * blockDim.x + threadIdx.x;
    if (i == 0) {
        int a = 1;
        for (int k = 0; k < 64; k++) if (ei_w[2 * k + 1] != 0) { a = 0; break; }
        g_ei64 = a;
        a = 1;
        for (int k = 0; k < 64; k++) if (b_w[49001 + 2 * k] != 0) { a = 0; break; }
        g_b64 = a;

        g_hp[0] = g_h0hi; g_hp[1] = g_h0lo;
        g_hp[2] = g_a1hi; g_hp[3] = g_a1lo;
        g_hp[4] = g_h1hi; g_hp[5] = g_h1lo;
        g_hp[6] = g_W1hi; g_hp[7] = g_W1lo;
        g_hp[8] = g_W2hi; g_hp[9] = g_W2lo;
    }
    if (i < 131072) {                       // W1: [n=256][k=512]
        int n = i >> 9, k = i & 511;
        float w = (k < 256) ? Wl1[k * 256 + n] : Wr1[(k - 256) * 256 + n];
        split_f32(w, g_W1hi[i], g_W1lo[i]);
    } else if (i < 196608) {                // W2: [n=256][k=256]
        int j = i - 131072;
        int n = j >> 8, k = j & 255;
        float w = (n < 128) ? Wl2[k * 128 + n] : Wr2[k * 128 + (n - 128)];
        split_f32(w, g_W2hi[j], g_W2lo[j]);
    }
    int stride = gridDim.x * blockDim.x;
    for (int j = i; j < N_NODES; j += stride) g_cnt[j] = 0;
    for (int j = i; j < N_GRAPHS * 128; j += stride) g_gsum[j] = 0.0f;
    for (int j = i; j < N_GRAPHS; j += stride) g_gcnt[j] = 0;
}

// ---------------- CSR build -------------------------------------------------
__global__ void k_count(const void* __restrict__ ei) {
    int is64 = g_ei64;
    int i = blockIdx.x * blockDim.x + threadIdx.x;
    int stride = gridDim.x * blockDim.x;
    for (int e = i; e < N_EDGES; e += stride) {
        int d = ld_idx(ei, (long long)N_EDGES + e, is64);
        atomicAdd(&g_cnt[d], 1);
    }
}

__global__ void k_scan1() {
    __shared__ int s[SCAN_B];
    int i = blockIdx.x * SCAN_B + threadIdx.x;
    int v = (i < N_NODES) ? g_cnt[i] : 0;
    s[threadIdx.x] = v;
    __syncthreads();
    for (int off = 1; off < SCAN_B; off <<= 1) {
        int t = (threadIdx.x >= off) ? s[threadIdx.x - off] : 0;
        __syncthreads();
        s[threadIdx.x] += t;
        __syncthreads();
    }
    if (i < N_NODES) g_rowstart[i] = s[threadIdx.x];
    if (threadIdx.x == SCAN_B - 1) g_bsums[blockIdx.x] = s[SCAN_B - 1];
}

// scan3 also does scan2's job: per-block prefix over the 49 block sums.
__global__ void k_scan3() {
    __shared__ int boff;
    int b = blockIdx.x;
    if (threadIdx.x == 0) {
        int run = 0;
        for (int j = 0; j < b; j++) run += g_bsums[j];
        boff = run;
    }
    __syncthreads();
    int i = b * SCAN_B + threadIdx.x;
    if (i >= N_NODES) return;
    int incl = g_rowstart[i];
    int excl = incl - g_cnt[i] + boff;
    g_rowstart[i] = excl;
    g_cursor[i] = excl;
}

__global__ void k_scatter(const void* __restrict__ ei) {
    int is64 = g_ei64;
    int i = blockIdx.x * blockDim.x + threadIdx.x;
    int stride = gridDim.x * blockDim.x;
    for (int e = i; e < N_EDGES; e += stride) {
        int s = ld_idx(ei, e, is64);
        int d = ld_idx(ei, (long long)N_EDGES + e, is64);
        int pos = atomicAdd(&g_cursor[d], 1);
        g_inlist[pos] = s;
    }
}

// ---------------- layer 0 (rank-1): warp per node ---------------------------
__global__ void k_layer0(const float* __restrict__ x,
                         const float* __restrict__ Wl0,
                         const float* __restrict__ b0,
                         const float* __restrict__ Wr0) {
    int wid = (blockIdx.x * blockDim.x + threadIdx.x) >> 5;
    int lane = threadIdx.x & 31;
    if (wid >= N_NODES) return;
    int deg = g_cnt[wid];
    int start = g_rowstart[wid];
    float s = 0.0f;
    for (int i = lane; i < deg; i += 32) s += x[g_inlist[start + i]];
    #pragma unroll
    for (int o = 16; o; o >>= 1) s += __shfl_xor_sync(0xFFFFFFFFu, s, o);
    float dinv = 1.0f / fmaxf((float)deg, 1.0f);
    if (lane == 0) g_dinv[wid] = dinv;
    float agg = s * dinv;
    float xv = x[wid];
    #pragma unroll
    for (int i = 0; i < 8; i++) {
        int f = i * 32 + lane;
        float v = fmaf(agg, Wl0[f], fmaf(xv, Wr0[f], b0[f]));
        v = fmaxf(v, 0.0f);
        __half hi, lo;
        split_f32(v, hi, lo);
        g_h0hi[wid * 256 + f] = hi;
        g_h0lo[wid * 256 + f] = lo;
    }
}

// ---------------- gather1 (known-good): block per node, half2 per feature ---
__global__ void k_gather1() {
    int n = blockIdx.x;
    int f2 = threadIdx.x;
    int deg = g_cnt[n];
    int start = g_rowstart[n];
    __shared__ int es[128];
    float ax = 0.0f, ay = 0.0f;
    for (int base = 0; base < deg; base += 128) {
        int m = min(128, deg - base);
        __syncthreads();
        if (f2 < m) es[f2] = g_inlist[start + base + f2];
        __syncthreads();
        for (int e = 0; e < m; e++) {
            int r = es[e];
            __half2 h = *(const __half2*)&g_h0hi[(size_t)r * 256 + 2 * f2];
            __half2 l = *(const __half2*)&g_h0lo[(size_t)r * 256 + 2 * f2];
            float2 fh = __half22float2(h);
            float2 fl = __half22float2(l);
            ax += fh.x + fl.x;
            ay += fh.y + fl.y;
        }
    }
    float dinv = g_dinv[n];
    ax *= dinv; ay *= dinv;
    __half hx, lx, hy, ly;
    split_f32(ax, hx, lx);
    split_f32(ay, hy, ly);
    *(__half2*)&g_a1hi[(size_t)n * 256 + 2 * f2] = __halves2half2(hx, hy);
    *(__half2*)&g_a1lo[(size_t)n * 256 + 2 * f2] = __halves2half2(lx, ly);
}

// ---------------- split-fp16 HMMA GEMM, BN=256, cp.async 2-stage ------------
// C[nrows x 256] = act([A0|A1] @ B^T + bias). One block owns the full 256-col
// output for its 128-row slab (A staged once). 512 threads = 16 warps (2m x 8n),
// warp tile 64x32, 3-term split: Ahi*Bhi + Ahi*Blo + Alo*Bhi.
__device__ __forceinline__ void mma16816(float* d, const unsigned* a, const unsigned* b) {
    asm volatile(
        "mma.sync.aligned.m16n8k16.row.col.f32.f16.f16.f32 "
        "{%0,%1,%2,%3}, {%4,%5,%6,%7}, {%8,%9}, {%0,%1,%2,%3};\n"
        : "+f"(d[0]), "+f"(d[1]), "+f"(d[2]), "+f"(d[3])
        : "r"(a[0]), "r"(a[1]), "r"(a[2]), "r"(a[3]), "r"(b[0]), "r"(b[1]));
}

__global__ void __launch_bounds__(512, 1)
k_hgemm(int sA0, int K0, int sA1, int K1, int sB,
        const float* __restrict__ bias, int bias_from, int relu,
        int outHalf, int sOutHi, int nrows) {
    const __half* A0h = g_hp[sA0];
    const __half* A0l = g_hp[sA0 + 1];
    const __half* A1h = (sA1 >= 0) ? g_hp[sA1] : (const __half*)0;
    const __half* A1l = (sA1 >= 0) ? g_hp[sA1 + 1] : (const __half*)0;
    const __half* Bh = g_hp[sB];
    const __half* Bl = g_hp[sB + 1];
    __half* Oh = outHalf ? g_hp[sOutHi] : (__half*)0;
    __half* Ol = outHalf ? g_hp[sOutHi + 1] : (__half*)0;

    extern __shared__ __half sm[];  // [2 stages][Ah | Al | Bh | Bl]

    int tid = threadIdx.x;
    int lane = tid & 31;
    int wid = tid >> 5;
    int wm = wid & 1;          // 2 m-slabs of 64 rows
    int wn = wid >> 1;         // 8 n-slabs of 32 cols
    int g = lane >> 2;
    int t2 = (lane & 3) * 2;
    int rowBase = blockIdx.x * 128;
    int K = K0 + K1;
    int NIT = K >> 5;

    float c[4][4][4];
    #pragma unroll
    for (int i = 0; i < 4; i++)
        #pragma unroll
        for (int j = 0; j < 4; j++)
            #pragma unroll
            for (int q = 0; q < 4; q++) c[i][j][q] = 0.0f;

    auto issue = [&](int iter) {
        int st = iter & 1;
        int k0 = iter << 5;
        __half* base = sm + st * SS;
        // A: 512 16B-segs per plane; one per thread
        {
            int r = tid >> 2;
            int kc = (tid & 3) * 8;
            int row = rowBase + r;
            int kk = k0 + kc;
            unsigned dh = smem_u32(&base[r * PA + kc]);
            unsigned dl = dh + PLANE_A * 2;
            if (row < nrows) {
                const __half *ph, *pl;
                if (kk < K0) {
                    ph = A0h + (size_t)row * K0 + kk;
                    pl = A0l + (size_t)row * K0 + kk;
                } else {
                    ph = A1h + (size_t)row * K1 + (kk - K0);
                    pl = A1l + (size_t)row * K1 + (kk - K0);
                }
                cp16(dh, ph);
                cp16(dl, pl);
            } else {
                uint4 z = make_uint4(0, 0, 0, 0);
                *(uint4*)&base[r * PA + kc] = z;
                *(uint4*)&base[PLANE_A + r * PA + kc] = z;
            }
        }
        // B: 1024 16B-segs per plane; two per thread
        #pragma unroll
        for (int it = 0; it < 2; it++) {
            int ch = tid + it * 512;
            int n = ch >> 2;
            int kc = (ch & 3) * 8;
            int kk = k0 + kc;
            unsigned dh = smem_u32(&base[2 * PLANE_A + n * PA + kc]);
            cp16(dh, Bh + (size_t)n * K + kk);
            cp16(dh + PLANE_B * 2, Bl + (size_t)n * K + kk);
        }
        asm volatile("cp.async.commit_group;\n" ::: "memory");
    };

    issue(0);

    for (int iter = 0; iter < NIT; iter++) {
        if (iter + 1 < NIT) {
            issue(iter + 1);
            asm volatile("cp.async.wait_group 1;\n" ::: "memory");
        } else {
            asm volatile("cp.async.wait_group 0;\n" ::: "memory");
        }
        __syncthreads();

        const __half* As0 = sm + (iter & 1) * SS;       // A hi
        const __half* As1 = As0 + PLANE_A;              // A lo
        const __half* Bs0 = As0 + 2 * PLANE_A;          // B hi
        const __half* Bs1 = Bs0 + PLANE_B;              // B lo

        #pragma unroll
        for (int ks = 0; ks < 2; ks++) {
            int kb = ks * 16;
            unsigned af[4][4], bfh[4][2], bfl[4][2];
            #pragma unroll
            for (int mt = 0; mt < 4; mt++) {
                int rb = wm * 64 + mt * 16;
                af[mt][0] = *(const unsigned*)&As0[(rb + g) * PA + kb + t2];
                af[mt][1] = *(const unsigned*)&As0[(rb + g + 8) * PA + kb + t2];
                af[mt][2] = *(const unsigned*)&As0[(rb + g) * PA + kb + t2 + 8];
                af[mt][3] = *(const unsigned*)&As0[(rb + g + 8) * PA + kb + t2 + 8];
            }
            #pragma unroll
            for (int nt = 0; nt < 4; nt++) {
                int nb = wn * 32 + nt * 8 + g;
                bfh[nt][0] = *(const unsigned*)&Bs0[nb * PA + kb + t2];
                bfh[nt][1] = *(const unsigned*)&Bs0[nb * PA + kb + t2 + 8];
                bfl[nt][0] = *(const unsigned*)&Bs1[nb * PA + kb + t2];
                bfl[nt][1] = *(const unsigned*)&Bs1[nb * PA + kb + t2 + 8];
            }
            #pragma unroll
            for (int mt = 0; mt < 4; mt++)
                #pragma unroll
                for (int nt = 0; nt < 4; nt++) {
                    mma16816(c[mt][nt], af[mt], bfh[nt]);
                    mma16816(c[mt][nt], af[mt], bfl[nt]);
                }
            #pragma unroll
            for (int mt = 0; mt < 4; mt++) {
                int rb = wm * 64 + mt * 16;
                af[mt][0] = *(const unsigned*)&As1[(rb + g) * PA + kb + t2];
                af[mt][1] = *(const unsigned*)&As1[(rb + g + 8) * PA + kb + t2];
                af[mt][2] = *(const unsigned*)&As1[(rb + g) * PA + kb + t2 + 8];
                af[mt][3] = *(const unsigned*)&As1[(rb + g + 8) * PA + kb + t2 + 8];
            }
            #pragma unroll
            for (int mt = 0; mt < 4; mt++)
                #pragma unroll
                for (int nt = 0; nt < 4; nt++)
                    mma16816(c[mt][nt], af[mt], bfh[nt]);
        }
        __syncthreads();
    }

    #pragma unroll
    for (int mt = 0; mt < 4; mt++) {
        #pragma unroll
        for (int nt = 0; nt < 4; nt++) {
            int r0 = rowBase + wm * 64 + mt * 16 + g;
            int cc = wn * 32 + nt * 8 + t2;
            float bv0 = 0.0f, bv1 = 0.0f;
            if (bias) {
                if (cc >= bias_from)     bv0 = bias[cc - bias_from];
                if (cc + 1 >= bias_from) bv1 = bias[cc + 1 - bias_from];
            }
            #pragma unroll
            for (int half_ : {0, 1}) {
                int row = r0 + half_ * 8;
                if (row >= nrows) continue;
                float v0 = c[mt][nt][half_ * 2 + 0] + bv0;
                float v1 = c[mt][nt][half_ * 2 + 1] + bv1;
                if (relu) { v0 = fmaxf(v0, 0.0f); v1 = fmaxf(v1, 0.0f); }
                if (outHalf) {
                    __half h0, l0, h1, l1;
                    split_f32(v0, h0, l0);
                    split_f32(v1, h1, l1);
                    *(__half2*)&Oh[(size_t)row * 256 + cc] = __halves2half2(h0, h1);
                    *(__half2*)&Ol[(size_t)row * 256 + cc] = __halves2half2(l0, l1);
                } else {
                    *(float2*)&g_pq[(size_t)row * 256 + cc] = make_float2(v0, v1);
                }
            }
        }
    }
}

// ---------------- final (known-good): block per node, 128 threads -----------
__global__ void k_final(const void* __restrict__ batch) {
    int n = blockIdx.x;
    int f = threadIdx.x;
    int deg = g_cnt[n];
    int start = g_rowstart[n];
    __shared__ int es[128];
    float acc = 0.0f;
    for (int base = 0; base < deg; base += 128) {
        int m = min(128, deg - base);
        __syncthreads();
        if (f < m) es[f] = g_inlist[start + base + f];
        __syncthreads();
        for (int e = 0; e < m; e++) acc += g_pq[(size_t)es[e] * 256 + f];
    }
    float h2 = acc * g_dinv[n] + g_pq[(size_t)n * 256 + 128 + f];
    int g = ld_idx(batch, n, g_b64);
    atomicAdd(&g_gsum[g * 128 + f], h2);
    if (f == 0) atomicAdd(&g_gcnt[g], 1);
}

// ---------------- layernorm over feature dim per graph ----------------------
__global__ void k_ln(const float* __restrict__ gamma,
                     const float* __restrict__ beta,
                     float* __restrict__ out) {
    int g = blockIdx.x;
    int f = threadIdx.x;
    __shared__ float sh[128];
    float v = g_gsum[g * 128 + f] / fmaxf((float)g_gcnt[g], 1.0f);

    sh[f] = v;
    __syncthreads();
    for (int o = 64; o; o >>= 1) {
        if (f < o) sh[f] += sh[f + o];
        __syncthreads();
    }
    float mean = sh[0] * (1.0f / 128.0f);
    __syncthreads();

    float d = v - mean;
    sh[f] = d * d;
    __syncthreads();
    for (int o = 64; o; o >>= 1) {
        if (f < o) sh[f] += sh[f + o];
        __syncthreads();
    }
    float var = sh[0] * (1.0f / 128.0f);

    out[g * 128 + f] = d * rsqrtf(var + 1e-5f) * gamma[f] + beta[f];
}

// ---------------- launch -----------------------------------------------------
extern "C" void kernel_launch(void* const* d_in, const int* in_sizes, int n_in,
                              void* d_out, int out_size) {
    const float* x     = (const float*)d_in[0];
    const void*  ei    = d_in[1];
    const void*  batch = d_in[2];
    const float* Wl0 = (const float*)d_in[3];
    const float* b0  = (const float*)d_in[4];
    const float* Wr0 = (const float*)d_in[5];
    const float* Wl1 = (const float*)d_in[6];
    const float* b1  = (const float*)d_in[7];
    const float* Wr1 = (const float*)d_in[8];
    const float* Wl2 = (const float*)d_in[9];
    const float* b2  = (const float*)d_in[10];
    const float* Wr2 = (const float*)d_in[11];
    const float* gamma = (const float*)d_in[12];
    const float* beta  = (const float*)d_in[13];
    float* out = (float*)d_out;

    // 120KB dynamic smem for the BN=256 pipelined GEMM
    cudaFuncSetAttribute(k_hgemm, cudaFuncAttributeMaxDynamicSharedMemorySize,
                         SMEM_BYTES);

    // setup: dtype detect, pointer table, zeroing, weight split
    k_setup<<<768, 256>>>((const int*)ei, (const int*)batch, Wl1, Wr1, Wl2, Wr2);

    // CSR build
    k_count<<<512, 256>>>(ei);
    k_scan1<<<NB_SCAN, SCAN_B>>>();
    k_scan3<<<NB_SCAN, SCAN_B>>>();
    k_scatter<<<512, 256>>>(ei);

    // layer 0 (rank-1) -> h0 planes
    k_layer0<<<(N_NODES * 32 + 255) / 256, 256>>>(x, Wl0, b0, Wr0);

    // layer 1: gather then h1 = relu([a1|h0] @ [Wl1;Wr1] + b1)
    k_gather1<<<N_NODES, 128>>>();
    k_hgemm<<<(N_NODES + 127) / 128, 512, SMEM_BYTES>>>(
        2, 256, 0, 256, 6, b1, 0, 1, 1, 4, N_NODES);

    // layer 2 fused: g_pq = h1 @ [Wl2 | Wr2], bias b2 on cols >= 128
    k_hgemm<<<(N_NODES + 127) / 128, 512, SMEM_BYTES>>>(
        4, 256, -1, 0, 8, b2, 128, 0, 0, 0, N_NODES);

    // aggregate p, add q, pool into graph sums
    k_final<<<N_NODES, 128>>>(batch);

    // layernorm
    k_ln<<<N_GRAPHS, 128>>>(gamma, beta, out);
}

// round 11
// speedup vs baseline: 1.0888x; 1.0888x over previous
#include <cuda_runtime.h>
#include <cuda_fp16.h>
#include <cstdint>
#include <math.h>

#define N_NODES  50000
#define N_EDGES  800000
#define N_GRAPHS 64
#define SCAN_B   1024
#define NB_SCAN  ((N_NODES + SCAN_B - 1) / SCAN_B)   // 49
#define PA 40                    // smem pitch in halves
#define PLANE (128 * PA)         // halves per plane tile
#define SS (4 * PLANE)           // halves per stage (A hi, A lo, B hi, B lo)
#define SMEM_BYTES (2 * SS * 2)  // 2 stages, 2 bytes/half = 81920

// ---------------- scratch (device globals; no allocation allowed) ----------
__device__ __align__(16) __half g_h0hi[N_NODES * 256];
__device__ __align__(16) __half g_h0lo[N_NODES * 256];
__device__ __align__(16) __half g_a1hi[N_NODES * 256];
__device__ __align__(16) __half g_a1lo[N_NODES * 256];
__device__ __align__(16) __half g_h1hi[N_NODES * 256];
__device__ __align__(16) __half g_h1lo[N_NODES * 256];
__device__ __align__(16) float  g_pq[N_NODES * 256];
__device__ __align__(16) __half g_W1hi[256 * 512];
__device__ __align__(16) __half g_W1lo[256 * 512];
__device__ __align__(16) __half g_W2hi[256 * 256];
__device__ __align__(16) __half g_W2lo[256 * 256];
__device__ __align__(8)  float2 g_ax[N_NODES];          // (agg0, x) per node
__device__ float g_dinv[N_NODES];
__device__ int   g_cnt[N_NODES];
__device__ int   g_rowstart[N_NODES];
__device__ int   g_cursor[N_NODES];
__device__ int   g_inlist[N_EDGES];
__device__ float g_gsum[N_GRAPHS * 128];
__device__ int   g_gcnt[N_GRAPHS];
__device__ int   g_bsums[64];

__device__ int     g_ei64;
__device__ int     g_b64;
__device__ __half* g_hp[10];  // 0:h0hi 1:h0lo 2:a1hi 3:a1lo 4:h1hi 5:h1lo 6:W1hi 7:W1lo 8:W2hi 9:W2lo

__device__ __forceinline__ int ld_idx(const void* p, long long i, int is64) {
    return is64 ? (int)((const long long*)p)[i] : ((const int*)p)[i];
}

__device__ __forceinline__ void split_f32(float v, __half& hi, __half& lo) {
    hi = __float2half_rn(v);
    lo = __float2half_rn(v - __half2float(hi));
}

__device__ __forceinline__ unsigned smem_u32(const void* p) {
    return (unsigned)__cvta_generic_to_shared(p);
}

__device__ __forceinline__ void cp16(unsigned dst, const void* src) {
    asm volatile("cp.async.cg.shared.global [%0], [%1], 16;\n" :: "r"(dst), "l"(src));
}

// ---------------- setup: dtype detect + pointers + zero + weight split ------
__global__ void k_setup(const int* ei_w, const int* b_w,
                        const float* __restrict__ Wl1, const float* __restrict__ Wr1,
                        const float* __restrict__ Wl2, const float* __restrict__ Wr2) {
    int i = blockIdx.x * blockDim.x + threadIdx.x;
    if (i == 0) {
        int a = 1;
        for (int k = 0; k < 64; k++) if (ei_w[2 * k + 1] != 0) { a = 0; break; }
        g_ei64 = a;
        a = 1;
        for (int k = 0; k < 64; k++) if (b_w[49001 + 2 * k] != 0) { a = 0; break; }
        g_b64 = a;

        g_hp[0] = g_h0hi; g_hp[1] = g_h0lo;
        g_hp[2] = g_a1hi; g_hp[3] = g_a1lo;
        g_hp[4] = g_h1hi; g_hp[5] = g_h1lo;
        g_hp[6] = g_W1hi; g_hp[7] = g_W1lo;
        g_hp[8] = g_W2hi; g_hp[9] = g_W2lo;
    }
    if (i < 131072) {                       // W1: [n=256][k=512]
        int n = i >> 9, k = i & 511;
        float w = (k < 256) ? Wl1[k * 256 + n] : Wr1[(k - 256) * 256 + n];
        split_f32(w, g_W1hi[i], g_W1lo[i]);
    } else if (i < 196608) {                // W2: [n=256][k=256]
        int j = i - 131072;
        int n = j >> 8, k = j & 255;
        float w = (n < 128) ? Wl2[k * 128 + n] : Wr2[k * 128 + (n - 128)];
        split_f32(w, g_W2hi[j], g_W2lo[j]);
    }
    int stride = gridDim.x * blockDim.x;
    for (int j = i; j < N_NODES; j += stride) g_cnt[j] = 0;
    for (int j = i; j < N_GRAPHS * 128; j += stride) g_gsum[j] = 0.0f;
    for (int j = i; j < N_GRAPHS; j += stride) g_gcnt[j] = 0;
}

// ---------------- CSR build -------------------------------------------------
__global__ void k_count(const void* __restrict__ ei) {
    int is64 = g_ei64;
    int i = blockIdx.x * blockDim.x + threadIdx.x;
    int stride = gridDim.x * blockDim.x;
    for (int e = i; e < N_EDGES; e += stride) {
        int d = ld_idx(ei, (long long)N_EDGES + e, is64);
        atomicAdd(&g_cnt[d], 1);
    }
}

__global__ void k_scan1() {
    __shared__ int s[SCAN_B];
    int i = blockIdx.x * SCAN_B + threadIdx.x;
    int v = (i < N_NODES) ? g_cnt[i] : 0;
    s[threadIdx.x] = v;
    __syncthreads();
    for (int off = 1; off < SCAN_B; off <<= 1) {
        int t = (threadIdx.x >= off) ? s[threadIdx.x - off] : 0;
        __syncthreads();
        s[threadIdx.x] += t;
        __syncthreads();
    }
    if (i < N_NODES) g_rowstart[i] = s[threadIdx.x];
    if (threadIdx.x == SCAN_B - 1) g_bsums[blockIdx.x] = s[SCAN_B - 1];
}

// scan3 also does scan2's job: per-block prefix over the 49 block sums.
__global__ void k_scan3() {
    __shared__ int boff;
    int b = blockIdx.x;
    if (threadIdx.x == 0) {
        int run = 0;
        for (int j = 0; j < b; j++) run += g_bsums[j];
        boff = run;
    }
    __syncthreads();
    int i = b * SCAN_B + threadIdx.x;
    if (i >= N_NODES) return;
    int incl = g_rowstart[i];
    int excl = incl - g_cnt[i] + boff;
    g_rowstart[i] = excl;
    g_cursor[i] = excl;
}

__global__ void k_scatter(const void* __restrict__ ei) {
    int is64 = g_ei64;
    int i = blockIdx.x * blockDim.x + threadIdx.x;
    int stride = gridDim.x * blockDim.x;
    for (int e = i; e < N_EDGES; e += stride) {
        int s = ld_idx(ei, e, is64);
        int d = ld_idx(ei, (long long)N_EDGES + e, is64);
        int pos = atomicAdd(&g_cursor[d], 1);
        g_inlist[pos] = s;
    }
}

// ---------------- layer 0 (rank-1): warp per node ---------------------------
// Also records the (agg0, x) scalar pair per node for the fused layer-1 gather.
__global__ void k_layer0(const float* __restrict__ x,
                         const float* __restrict__ Wl0,
                         const float* __restrict__ b0,
                         const float* __restrict__ Wr0) {
    int wid = (blockIdx.x * blockDim.x + threadIdx.x) >> 5;
    int lane = threadIdx.x & 31;
    if (wid >= N_NODES) return;
    int deg = g_cnt[wid];
    int start = g_rowstart[wid];
    float s = 0.0f;
    for (int i = lane; i < deg; i += 32) s += x[g_inlist[start + i]];
    #pragma unroll
    for (int o = 16; o; o >>= 1) s += __shfl_xor_sync(0xFFFFFFFFu, s, o);
    float dinv = 1.0f / fmaxf((float)deg, 1.0f);
    float agg = s * dinv;
    float xv = x[wid];
    if (lane == 0) {
        g_dinv[wid] = dinv;
        g_ax[wid] = make_float2(agg, xv);
    }
    #pragma unroll
    for (int i = 0; i < 8; i++) {
        int f = i * 32 + lane;
        float v = fmaf(agg, Wl0[f], fmaf(xv, Wr0[f], b0[f]));
        v = fmaxf(v, 0.0f);
        __half hi, lo;
        split_f32(v, hi, lo);
        g_h0hi[wid * 256 + f] = hi;
        g_h0lo[wid * 256 + f] = lo;
    }
}

// ---------------- gather1: block per node, recompute h0 from scalars --------
// Same staging structure as the proven round-4 gather (128 threads, smem tile,
// broadcast inner loop) but stages 8-byte (agg0,x) pairs instead of reading the
// 2KB h0 feature rows -- all global edge traffic replaced by FMA recompute:
//   agg1[d][f] = dinv_d * sum_s relu(agg0_s*Wl0[f] + x_s*Wr0[f] + b0[f])
__global__ void k_gather1(const float* __restrict__ Wl0,
                          const float* __restrict__ b0,
                          const float* __restrict__ Wr0) {
    int n = blockIdx.x;
    int f2 = threadIdx.x;                 // features 2*f2, 2*f2+1
    int deg = g_cnt[n];
    int start = g_rowstart[n];

    float wl0 = Wl0[2 * f2], wl1 = Wl0[2 * f2 + 1];
    float wr0 = Wr0[2 * f2], wr1 = Wr0[2 * f2 + 1];
    float bb0 = b0[2 * f2],  bb1 = b0[2 * f2 + 1];

    __shared__ float2 es[128];
    float a0 = 0.0f, a1 = 0.0f;
    for (int base = 0; base < deg; base += 128) {
        int m = min(128, deg - base);
        __syncthreads();
        if (f2 < m) es[f2] = g_ax[g_inlist[start + base + f2]];
        __syncthreads();
        for (int e = 0; e < m; e++) {
            float2 ax = es[e];
            a0 += fmaxf(fmaf(ax.x, wl0, fmaf(ax.y, wr0, bb0)), 0.0f);
            a1 += fmaxf(fmaf(ax.x, wl1, fmaf(ax.y, wr1, bb1)), 0.0f);
        }
    }
    float dinv = g_dinv[n];
    a0 *= dinv; a1 *= dinv;
    __half hx, lx, hy, ly;
    split_f32(a0, hx, lx);
    split_f32(a1, hy, ly);
    *(__half2*)&g_a1hi[(size_t)n * 256 + 2 * f2] = __halves2half2(hx, hy);
    *(__half2*)&g_a1lo[(size_t)n * 256 + 2 * f2] = __halves2half2(lx, ly);
}

// ---------------- split-fp16 HMMA GEMM (round-7 proven): cp.async 2-stage ---
__device__ __forceinline__ void mma16816(float* d, const unsigned* a, const unsigned* b) {
    asm volatile(
        "mma.sync.aligned.m16n8k16.row.col.f32.f16.f16.f32 "
        "{%0,%1,%2,%3}, {%4,%5,%6,%7}, {%8,%9}, {%0,%1,%2,%3};\n"
        : "+f"(d[0]), "+f"(d[1]), "+f"(d[2]), "+f"(d[3])
        : "r"(a[0]), "r"(a[1]), "r"(a[2]), "r"(a[3]), "r"(b[0]), "r"(b[1]));
}

__global__ void __launch_bounds__(256, 2)
k_hgemm(int sA0, int K0, int sA1, int K1, int sB,
        const float* __restrict__ bias, int bias_from, int relu,
        int outHalf, int sOutHi, int nrows, int ncols) {
    const __half* A0h = g_hp[sA0];
    const __half* A0l = g_hp[sA0 + 1];
    const __half* A1h = (sA1 >= 0) ? g_hp[sA1] : (const __half*)0;
    const __half* A1l = (sA1 >= 0) ? g_hp[sA1 + 1] : (const __half*)0;
    const __half* Bh = g_hp[sB];
    const __half* Bl = g_hp[sB + 1];
    __half* Oh = outHalf ? g_hp[sOutHi] : (__half*)0;
    __half* Ol = outHalf ? g_hp[sOutHi + 1] : (__half*)0;

    extern __shared__ __half sm[];   // [2 stages][A hi | A lo | B hi | B lo]

    int tid = threadIdx.x;
    int lane = tid & 31;
    int wid = tid >> 5;
    int wm = wid & 1;
    int wn = wid >> 1;
    int g = lane >> 2;
    int t2 = (lane & 3) * 2;
    int rowBase = blockIdx.y * 128;
    int colBase = blockIdx.x * 128;
    int K = K0 + K1;
    int NIT = K >> 5;

    int r_[2], kc_[2];
    #pragma unroll
    for (int it = 0; it < 2; it++) {
        int ch = tid + it * 256;
        r_[it] = ch >> 2;
        kc_[it] = (ch & 3) * 8;
    }

    float c[4][4][4];
    #pragma unroll
    for (int i = 0; i < 4; i++)
        #pragma unroll
        for (int j = 0; j < 4; j++)
            #pragma unroll
            for (int q = 0; q < 4; q++) c[i][j][q] = 0.0f;

    auto issue = [&](int iter) {
        int st = iter & 1;
        int k0 = iter << 5;
        __half* base = sm + st * SS;
        #pragma unroll
        for (int it = 0; it < 2; it++) {
            int r = r_[it], kc = kc_[it];
            int row = rowBase + r;
            int kk = k0 + kc;
            unsigned dh = smem_u32(&base[r * PA + kc]);
            unsigned dl = dh + PLANE * 2;
            if (row < nrows) {
                const __half *ph, *pl;
                if (kk < K0) {
                    ph = A0h + (size_t)row * K0 + kk;
                    pl = A0l + (size_t)row * K0 + kk;
                } else {
                    ph = A1h + (size_t)row * K1 + (kk - K0);
                    pl = A1l + (size_t)row * K1 + (kk - K0);
                }
                cp16(dh, ph);
                cp16(dl, pl);
            } else {
                uint4 z = make_uint4(0, 0, 0, 0);
                *(uint4*)&base[r * PA + kc] = z;
                *(uint4*)&base[PLANE + r * PA + kc] = z;
            }
        }
        #pragma unroll
        for (int it = 0; it < 2; it++) {
            int n = r_[it], kc = kc_[it];
            int col = colBase + n;
            int kk = k0 + kc;
            unsigned dh = smem_u32(&base[2 * PLANE + n * PA + kc]);
            cp16(dh, Bh + (size_t)col * K + kk);
            cp16(dh + PLANE * 2, Bl + (size_t)col * K + kk);
        }
        asm volatile("cp.async.commit_group;\n" ::: "memory");
    };

    issue(0);

    for (int iter = 0; iter < NIT; iter++) {
        if (iter + 1 < NIT) {
            issue(iter + 1);
            asm volatile("cp.async.wait_group 1;\n" ::: "memory");
        } else {
            asm volatile("cp.async.wait_group 0;\n" ::: "memory");
        }
        __syncthreads();

        const __half* As0 = sm + (iter & 1) * SS;
        const __half* As1 = As0 + PLANE;
        const __half* Bs0 = As0 + 2 * PLANE;
        const __half* Bs1 = As0 + 3 * PLANE;

        #pragma unroll
        for (int ks = 0; ks < 2; ks++) {
            int kb = ks * 16;
            unsigned af[4][4], bfh[4][2], bfl[4][2];
            #pragma unroll
            for (int mt = 0; mt < 4; mt++) {
                int rb = wm * 64 + mt * 16;
                af[mt][0] = *(const unsigned*)&As0[(rb + g) * PA + kb + t2];
                af[mt][1] = *(const unsigned*)&As0[(rb + g + 8) * PA + kb + t2];
                af[mt][2] = *(const unsigned*)&As0[(rb + g) * PA + kb + t2 + 8];
                af[mt][3] = *(const unsigned*)&As0[(rb + g + 8) * PA + kb + t2 + 8];
            }
            #pragma unroll
            for (int nt = 0; nt < 4; nt++) {
                int nb = wn * 32 + nt * 8 + g;
                bfh[nt][0] = *(const unsigned*)&Bs0[nb * PA + kb + t2];
                bfh[nt][1] = *(const unsigned*)&Bs0[nb * PA + kb + t2 + 8];
                bfl[nt][0] = *(const unsigned*)&Bs1[nb * PA + kb + t2];
                bfl[nt][1] = *(const unsigned*)&Bs1[nb * PA + kb + t2 + 8];
            }
            #pragma unroll
            for (int mt = 0; mt < 4; mt++)
                #pragma unroll
                for (int nt = 0; nt < 4; nt++) {
                    mma16816(c[mt][nt], af[mt], bfh[nt]);
                    mma16816(c[mt][nt], af[mt], bfl[nt]);
                }
            #pragma unroll
            for (int mt = 0; mt < 4; mt++) {
                int rb = wm * 64 + mt * 16;
                af[mt][0] = *(const unsigned*)&As1[(rb + g) * PA + kb + t2];
                af[mt][1] = *(const unsigned*)&As1[(rb + g + 8) * PA + kb + t2];
                af[mt][2] = *(const unsigned*)&As1[(rb + g) * PA + kb + t2 + 8];
                af[mt][3] = *(const unsigned*)&As1[(rb + g + 8) * PA + kb + t2 + 8];
            }
            #pragma unroll
            for (int mt = 0; mt < 4; mt++)
                #pragma unroll
                for (int nt = 0; nt < 4; nt++)
                    mma16816(c[mt][nt], af[mt], bfh[nt]);
        }
        __syncthreads();
    }

    #pragma unroll
    for (int mt = 0; mt < 4; mt++) {
        #pragma unroll
        for (int nt = 0; nt < 4; nt++) {
            int r0 = rowBase + wm * 64 + mt * 16 + g;
            int cc = colBase + wn * 32 + nt * 8 + t2;
            float bv0 = 0.0f, bv1 = 0.0f;
            if (bias) {
                if (cc >= bias_from)     bv0 = bias[cc - bias_from];
                if (cc + 1 >= bias_from) bv1 = bias[cc + 1 - bias_from];
            }
            #pragma unroll
            for (int half_ : {0, 1}) {
                int row = r0 + half_ * 8;
                if (row >= nrows) continue;
                float v0 = c[mt][nt][half_ * 2 + 0] + bv0;
                float v1 = c[mt][nt][half_ * 2 + 1] + bv1;
                if (relu) { v0 = fmaxf(v0, 0.0f); v1 = fmaxf(v1, 0.0f); }
                if (outHalf) {
                    __half h0, l0, h1, l1;
                    split_f32(v0, h0, l0);
                    split_f32(v1, h1, l1);
                    *(__half2*)&Oh[(size_t)row * ncols + cc] = __halves2half2(h0, h1);
                    *(__half2*)&Ol[(size_t)row * ncols + cc] = __halves2half2(l0, l1);
                } else {
                    *(float2*)&g_pq[(size_t)row * ncols + cc] = make_float2(v0, v1);
                }
            }
        }
    }
}

// ---------------- final (known-good): block per node, 128 threads -----------
__global__ void k_final(const void* __restrict__ batch) {
    int n = blockIdx.x;
    int f = threadIdx.x;
    int deg = g_cnt[n];
    int start = g_rowstart[n];
    __shared__ int es[128];
    float acc = 0.0f;
    for (int base = 0; base < deg; base += 128) {
        int m = min(128, deg - base);
        __syncthreads();
        if (f < m) es[f] = g_inlist[start + base + f];
        __syncthreads();
        for (int e = 0; e < m; e++) acc += g_pq[(size_t)es[e] * 256 + f];
    }
    float h2 = acc * g_dinv[n] + g_pq[(size_t)n * 256 + 128 + f];
    int g = ld_idx(batch, n, g_b64);
    atomicAdd(&g_gsum[g * 128 + f], h2);
    if (f == 0) atomicAdd(&g_gcnt[g], 1);
}

// ---------------- layernorm over feature dim per graph ----------------------
__global__ void k_ln(const float* __restrict__ gamma,
                     const float* __restrict__ beta,
                     float* __restrict__ out) {
    int g = blockIdx.x;
    int f = threadIdx.x;
    __shared__ float sh[128];
    float v = g_gsum[g * 128 + f] / fmaxf((float)g_gcnt[g], 1.0f);

    sh[f] = v;
    __syncthreads();
    for (int o = 64; o; o >>= 1) {
        if (f < o) sh[f] += sh[f + o];
        __syncthreads();
    }
    float mean = sh[0] * (1.0f / 128.0f);
    __syncthreads();

    float d = v - mean;
    sh[f] = d * d;
    __syncthreads();
    for (int o = 64; o; o >>= 1) {
        if (f < o) sh[f] += sh[f + o];
        __syncthreads();
    }
    float var = sh[0] * (1.0f / 128.0f);

    out[g * 128 + f] = d * rsqrtf(var + 1e-5f) * gamma[f] + beta[f];
}

// ---------------- launch -----------------------------------------------------
extern "C" void kernel_launch(void* const* d_in, const int* in_sizes, int n_in,
                              void* d_out, int out_size) {
    const float* x     = (const float*)d_in[0];
    const void*  ei    = d_in[1];
    const void*  batch = d_in[2];
    const float* Wl0 = (const float*)d_in[3];
    const float* b0  = (const float*)d_in[4];
    const float* Wr0 = (const float*)d_in[5];
    const float* Wl1 = (const float*)d_in[6];
    const float* b1  = (const float*)d_in[7];
    const float* Wr1 = (const float*)d_in[8];
    const float* Wl2 = (const float*)d_in[9];
    const float* b2  = (const float*)d_in[10];
    const float* Wr2 = (const float*)d_in[11];
    const float* gamma = (const float*)d_in[12];
    const float* beta  = (const float*)d_in[13];
    float* out = (float*)d_out;

    cudaFuncSetAttribute(k_hgemm, cudaFuncAttributeMaxDynamicSharedMemorySize,
                         SMEM_BYTES);

    // setup: dtype detect, pointer table, zeroing, weight split
    k_setup<<<768, 256>>>((const int*)ei, (const int*)batch, Wl1, Wr1, Wl2, Wr2);

    // CSR build
    k_count<<<512, 256>>>(ei);
    k_scan1<<<NB_SCAN, SCAN_B>>>();
    k_scan3<<<NB_SCAN, SCAN_B>>>();
    k_scatter<<<512, 256>>>(ei);

    // layer 0 (rank-1) -> h0 planes + (agg0, x) scalars
    k_layer0<<<(N_NODES * 32 + 255) / 256, 256>>>(x, Wl0, b0, Wr0);

    // layer 1: scalar-recompute gather then h1 = relu([a1|h0] @ [Wl1;Wr1] + b1)
    k_gather1<<<N_NODES, 128>>>(Wl0, b0, Wr0);
    {
        dim3 grid(2, (N_NODES + 127) / 128);
        k_hgemm<<<grid, 256, SMEM_BYTES>>>(2, 256, 0, 256, 6, b1, 0, 1, 1, 4,
                                           N_NODES, 256);
    }

    // layer 2 fused: g_pq = h1 @ [Wl2 | Wr2], bias b2 on cols >= 128
    {
        dim3 grid(2, (N_NODES + 127) / 128);
        k_hgemm<<<grid, 256, SMEM_BYTES>>>(4, 256, -1, 0, 8, b2, 128, 0, 0, 0,
                                           N_NODES, 256);
    }

    // aggregate p, add q, pool into graph sums
    k_final<<<N_NODES, 128>>>(batch);

    // layernorm
    k_ln<<<N_GRAPHS, 128>>>(gamma, beta, out);
}

// round 12
// speedup vs baseline: 1.3014x; 1.1953x over previous
#include <cuda_runtime.h>
#include <cuda_fp16.h>
#include <cstdint>
#include <math.h>

#define N_NODES  50000
#define N_EDGES  800000
#define N_GRAPHS 64
#define SCAN_B   1024
#define NB_SCAN  ((N_NODES + SCAN_B - 1) / SCAN_B)   // 49
#define PA 40                    // smem pitch in halves
#define PLANE (128 * PA)         // halves per plane tile
#define SS (3 * PLANE)           // halves per stage (A hi, B hi, B lo)
#define SMEM_BYTES (2 * SS * 2)  // 2 stages, 2 bytes/half = 61440

// ---------------- scratch (device globals; no allocation allowed) ----------
__device__ __align__(16) __half g_h0hi[N_NODES * 256];
__device__ __align__(16) __half g_a1hi[N_NODES * 256];
__device__ __align__(16) __half g_h1hi[N_NODES * 256];
__device__ __align__(16) float  g_pq[N_NODES * 256];
__device__ __align__(16) __half g_W1hi[256 * 512];
__device__ __align__(16) __half g_W1lo[256 * 512];
__device__ __align__(16) __half g_W2hi[256 * 256];
__device__ __align__(16) __half g_W2lo[256 * 256];
__device__ __align__(8)  float2 g_ax[N_NODES];          // (agg0, x) per node
__device__ float g_dinv[N_NODES];
__device__ int   g_cnt[N_NODES];
__device__ int   g_rowstart[N_NODES];
__device__ int   g_cursor[N_NODES];
__device__ int   g_inlist[N_EDGES];
__device__ float g_gsum[N_GRAPHS * 128];
__device__ int   g_gcnt[N_GRAPHS];
__device__ int   g_bsums[64];

__device__ int     g_ei64;
__device__ int     g_b64;
__device__ __half* g_hp[8];   // 0:h0hi 1:a1hi 2:h1hi 3:- 4:W1hi 5:W1lo 6:W2hi 7:W2lo

__device__ __forceinline__ int ld_idx(const void* p, long long i, int is64) {
    return is64 ? (int)((const long long*)p)[i] : ((const int*)p)[i];
}

__device__ __forceinline__ void split_f32(float v, __half& hi, __half& lo) {
    hi = __float2half_rn(v);
    lo = __float2half_rn(v - __half2float(hi));
}

__device__ __forceinline__ unsigned smem_u32(const void* p) {
    return (unsigned)__cvta_generic_to_shared(p);
}

__device__ __forceinline__ void cp16(unsigned dst, const void* src) {
    asm volatile("cp.async.cg.shared.global [%0], [%1], 16;\n" :: "r"(dst), "l"(src));
}

// ---------------- setup: dtype detect + pointers + zero + weight split ------
__global__ void k_setup(const int* ei_w, const int* b_w,
                        const float* __restrict__ Wl1, const float* __restrict__ Wr1,
                        const float* __restrict__ Wl2, const float* __restrict__ Wr2) {
    int i = blockIdx.x * blockDim.x + threadIdx.x;
    if (i == 0) {
        int a = 1;
        for (int k = 0; k < 64; k++) if (ei_w[2 * k + 1] != 0) { a = 0; break; }
        g_ei64 = a;
        a = 1;
        for (int k = 0; k < 64; k++) if (b_w[49001 + 2 * k] != 0) { a = 0; break; }
        g_b64 = a;

        g_hp[0] = g_h0hi; g_hp[1] = g_a1hi;
        g_hp[2] = g_h1hi; g_hp[3] = (__half*)0;
        g_hp[4] = g_W1hi; g_hp[5] = g_W1lo;
        g_hp[6] = g_W2hi; g_hp[7] = g_W2lo;
    }
    if (i < 131072) {                       // W1: [n=256][k=512]
        int n = i >> 9, k = i & 511;
        float w = (k < 256) ? Wl1[k * 256 + n] : Wr1[(k - 256) * 256 + n];
        split_f32(w, g_W1hi[i], g_W1lo[i]);
    } else if (i < 196608) {                // W2: [n=256][k=256]
        int j = i - 131072;
        int n = j >> 8, k = j & 255;
        float w = (n < 128) ? Wl2[k * 128 + n] : Wr2[k * 128 + (n - 128)];
        split_f32(w, g_W2hi[j], g_W2lo[j]);
    }
    int stride = gridDim.x * blockDim.x;
    for (int j = i; j < N_NODES; j += stride) g_cnt[j] = 0;
    for (int j = i; j < N_GRAPHS * 128; j += stride) g_gsum[j] = 0.0f;
    for (int j = i; j < N_GRAPHS; j += stride) g_gcnt[j] = 0;
}

// ---------------- CSR build -------------------------------------------------
__global__ void k_count(const void* __restrict__ ei) {
    int is64 = g_ei64;
    int i = blockIdx.x * blockDim.x + threadIdx.x;
    int stride = gridDim.x * blockDim.x;
    for (int e = i; e < N_EDGES; e += stride) {
        int d = ld_idx(ei, (long long)N_EDGES + e, is64);
        atomicAdd(&g_cnt[d], 1);
    }
}

__global__ void k_scan1() {
    __shared__ int s[SCAN_B];
    int i = blockIdx.x * SCAN_B + threadIdx.x;
    int v = (i < N_NODES) ? g_cnt[i] : 0;
    s[threadIdx.x] = v;
    __syncthreads();
    for (int off = 1; off < SCAN_B; off <<= 1) {
        int t = (threadIdx.x >= off) ? s[threadIdx.x - off] : 0;
        __syncthreads();
        s[threadIdx.x] += t;
        __syncthreads();
    }
    if (i < N_NODES) g_rowstart[i] = s[threadIdx.x];
    if (threadIdx.x == SCAN_B - 1) g_bsums[blockIdx.x] = s[SCAN_B - 1];
}

// scan3 also does scan2's job: per-block prefix over the 49 block sums.
__global__ void k_scan3() {
    __shared__ int boff;
    int b = blockIdx.x;
    if (threadIdx.x == 0) {
        int run = 0;
        for (int j = 0; j < b; j++) run += g_bsums[j];
        boff = run;
    }
    __syncthreads();
    int i = b * SCAN_B + threadIdx.x;
    if (i >= N_NODES) return;
    int incl = g_rowstart[i];
    int excl = incl - g_cnt[i] + boff;
    g_rowstart[i] = excl;
    g_cursor[i] = excl;
}

__global__ void k_scatter(const void* __restrict__ ei) {
    int is64 = g_ei64;
    int i = blockIdx.x * blockDim.x + threadIdx.x;
    int stride = gridDim.x * blockDim.x;
    for (int e = i; e < N_EDGES; e += stride) {
        int s = ld_idx(ei, e, is64);
        int d = ld_idx(ei, (long long)N_EDGES + e, is64);
        int pos = atomicAdd(&g_cursor[d], 1);
        g_inlist[pos] = s;
    }
}

// ---------------- layer 0 (rank-1): warp per node ---------------------------
// Also records the (agg0, x) scalar pair per node for the fused layer-1 gather.
__global__ void k_layer0(const float* __restrict__ x,
                         const float* __restrict__ Wl0,
                         const float* __restrict__ b0,
                         const float* __restrict__ Wr0) {
    int wid = (blockIdx.x * blockDim.x + threadIdx.x) >> 5;
    int lane = threadIdx.x & 31;
    if (wid >= N_NODES) return;
    int deg = g_cnt[wid];
    int start = g_rowstart[wid];
    float s = 0.0f;
    for (int i = lane; i < deg; i += 32) s += x[g_inlist[start + i]];
    #pragma unroll
    for (int o = 16; o; o >>= 1) s += __shfl_xor_sync(0xFFFFFFFFu, s, o);
    float dinv = 1.0f / fmaxf((float)deg, 1.0f);
    float agg = s * dinv;
    float xv = x[wid];
    if (lane == 0) {
        g_dinv[wid] = dinv;
        g_ax[wid] = make_float2(agg, xv);
    }
    #pragma unroll
    for (int i = 0; i < 8; i++) {
        int f = i * 32 + lane;
        float v = fmaf(agg, Wl0[f], fmaf(xv, Wr0[f], b0[f]));
        g_h0hi[wid * 256 + f] = __float2half_rn(fmaxf(v, 0.0f));
    }
}

// ---------------- gather1: block per node, recompute h0 from scalars --------
__global__ void k_gather1(const float* __restrict__ Wl0,
                          const float* __restrict__ b0,
                          const float* __restrict__ Wr0) {
    int n = blockIdx.x;
    int f2 = threadIdx.x;                 // features 2*f2, 2*f2+1
    int deg = g_cnt[n];
    int start = g_rowstart[n];

    float wl0 = Wl0[2 * f2], wl1 = Wl0[2 * f2 + 1];
    float wr0 = Wr0[2 * f2], wr1 = Wr0[2 * f2 + 1];
    float bb0 = b0[2 * f2],  bb1 = b0[2 * f2 + 1];

    __shared__ float2 es[128];
    float a0 = 0.0f, a1 = 0.0f;
    for (int base = 0; base < deg; base += 128) {
        int m = min(128, deg - base);
        __syncthreads();
        if (f2 < m) es[f2] = g_ax[g_inlist[start + base + f2]];
        __syncthreads();
        for (int e = 0; e < m; e++) {
            float2 ax = es[e];
            a0 += fmaxf(fmaf(ax.x, wl0, fmaf(ax.y, wr0, bb0)), 0.0f);
            a1 += fmaxf(fmaf(ax.x, wl1, fmaf(ax.y, wr1, bb1)), 0.0f);
        }
    }
    float dinv = g_dinv[n];
    *(__half2*)&g_a1hi[(size_t)n * 256 + 2 * f2] =
        __halves2half2(__float2half_rn(a0 * dinv), __float2half_rn(a1 * dinv));
}

// ---------------- 2-term split HMMA GEMM: C = act(Ahi @ (Bhi+Blo)^T + bias) -
// A activations fp16 (hi plane only), B weights split hi+lo. cp.async 2-stage.
__device__ __forceinline__ void mma16816(float* d, const unsigned* a, const unsigned* b) {
    asm volatile(
        "mma.sync.aligned.m16n8k16.row.col.f32.f16.f16.f32 "
        "{%0,%1,%2,%3}, {%4,%5,%6,%7}, {%8,%9}, {%0,%1,%2,%3};\n"
        : "+f"(d[0]), "+f"(d[1]), "+f"(d[2]), "+f"(d[3])
        : "r"(a[0]), "r"(a[1]), "r"(a[2]), "r"(a[3]), "r"(b[0]), "r"(b[1]));
}

__global__ void __launch_bounds__(256, 2)
k_hgemm(int sA0, int K0, int sA1, int K1, int sB,
        const float* __restrict__ bias, int bias_from, int relu,
        int outHalf, int sOut, int nrows, int ncols) {
    const __half* A0h = g_hp[sA0];
    const __half* A1h = (sA1 >= 0) ? g_hp[sA1] : (const __half*)0;
    const __half* Bh = g_hp[sB];
    const __half* Bl = g_hp[sB + 1];
    __half* Oh = outHalf ? g_hp[sOut] : (__half*)0;

    extern __shared__ __half sm[];   // [2 stages][A hi | B hi | B lo]

    int tid = threadIdx.x;
    int lane = tid & 31;
    int wid = tid >> 5;
    int wm = wid & 1;
    int wn = wid >> 1;
    int g = lane >> 2;
    int t2 = (lane & 3) * 2;
    int rowBase = blockIdx.y * 128;
    int colBase = blockIdx.x * 128;
    int K = K0 + K1;
    int NIT = K >> 5;

    int r_[2], kc_[2];
    #pragma unroll
    for (int it = 0; it < 2; it++) {
        int ch = tid + it * 256;
        r_[it] = ch >> 2;
        kc_[it] = (ch & 3) * 8;
    }

    float c[4][4][4];
    #pragma unroll
    for (int i = 0; i < 4; i++)
        #pragma unroll
        for (int j = 0; j < 4; j++)
            #pragma unroll
            for (int q = 0; q < 4; q++) c[i][j][q] = 0.0f;

    auto issue = [&](int iter) {
        int st = iter & 1;
        int k0 = iter << 5;
        __half* base = sm + st * SS;
        #pragma unroll
        for (int it = 0; it < 2; it++) {
            int r = r_[it], kc = kc_[it];
            int row = rowBase + r;
            int kk = k0 + kc;
            unsigned dh = smem_u32(&base[r * PA + kc]);
            if (row < nrows) {
                const __half* ph = (kk < K0)
                    ? (A0h + (size_t)row * K0 + kk)
                    : (A1h + (size_t)row * K1 + (kk - K0));
                cp16(dh, ph);
            } else {
                *(uint4*)&base[r * PA + kc] = make_uint4(0, 0, 0, 0);
            }
        }
        #pragma unroll
        for (int it = 0; it < 2; it++) {
            int n = r_[it], kc = kc_[it];
            int col = colBase + n;
            int kk = k0 + kc;
            unsigned dh = smem_u32(&base[PLANE + n * PA + kc]);
            cp16(dh, Bh + (size_t)col * K + kk);
            cp16(dh + PLANE * 2, Bl + (size_t)col * K + kk);
        }
        asm volatile("cp.async.commit_group;\n" ::: "memory");
    };

    issue(0);

    for (int iter = 0; iter < NIT; iter++) {
        if (iter + 1 < NIT) {
            issue(iter + 1);
            asm volatile("cp.async.wait_group 1;\n" ::: "memory");
        } else {
            asm volatile("cp.async.wait_group 0;\n" ::: "memory");
        }
        __syncthreads();

        const __half* As0 = sm + (iter & 1) * SS;       // A hi
        const __half* Bs0 = As0 + PLANE;                // B hi
        const __half* Bs1 = As0 + 2 * PLANE;            // B lo

        #pragma unroll
        for (int ks = 0; ks < 2; ks++) {
            int kb = ks * 16;
            unsigned af[4][4], bfh[4][2], bfl[4][2];
            #pragma unroll
            for (int mt = 0; mt < 4; mt++) {
                int rb = wm * 64 + mt * 16;
                af[mt][0] = *(const unsigned*)&As0[(rb + g) * PA + kb + t2];
                af[mt][1] = *(const unsigned*)&As0[(rb + g + 8) * PA + kb + t2];
                af[mt][2] = *(const unsigned*)&As0[(rb + g) * PA + kb + t2 + 8];
                af[mt][3] = *(const unsigned*)&As0[(rb + g + 8) * PA + kb + t2 + 8];
            }
            #pragma unroll
            for (int nt = 0; nt < 4; nt++) {
                int nb = wn * 32 + nt * 8 + g;
                bfh[nt][0] = *(const unsigned*)&Bs0[nb * PA + kb + t2];
                bfh[nt][1] = *(const unsigned*)&Bs0[nb * PA + kb + t2 + 8];
                bfl[nt][0] = *(const unsigned*)&Bs1[nb * PA + kb + t2];
                bfl[nt][1] = *(const unsigned*)&Bs1[nb * PA + kb + t2 + 8];
            }
            #pragma unroll
            for (int mt = 0; mt < 4; mt++)
                #pragma unroll
                for (int nt = 0; nt < 4; nt++) {
                    mma16816(c[mt][nt], af[mt], bfh[nt]);
                    mma16816(c[mt][nt], af[mt], bfl[nt]);
                }
        }
        __syncthreads();
    }

    #pragma unroll
    for (int mt = 0; mt < 4; mt++) {
        #pragma unroll
        for (int nt = 0; nt < 4; nt++) {
            int r0 = rowBase + wm * 64 + mt * 16 + g;
            int cc = colBase + wn * 32 + nt * 8 + t2;
            float bv0 = 0.0f, bv1 = 0.0f;
            if (bias) {
                if (cc >= bias_from)     bv0 = bias[cc - bias_from];
                if (cc + 1 >= bias_from) bv1 = bias[cc + 1 - bias_from];
            }
            #pragma unroll
            for (int half_ : {0, 1}) {
                int row = r0 + half_ * 8;
                if (row >= nrows) continue;
                float v0 = c[mt][nt][half_ * 2 + 0] + bv0;
                float v1 = c[mt][nt][half_ * 2 + 1] + bv1;
                if (relu) { v0 = fmaxf(v0, 0.0f); v1 = fmaxf(v1, 0.0f); }
                if (outHalf) {
                    *(__half2*)&Oh[(size_t)row * ncols + cc] =
                        __halves2half2(__float2half_rn(v0), __float2half_rn(v1));
                } else {
                    *(float2*)&g_pq[(size_t)row * ncols + cc] = make_float2(v0, v1);
                }
            }
        }
    }
}

// ---------------- final (known-good): block per node, 128 threads -----------
__global__ void k_final(const void* __restrict__ batch) {
    int n = blockIdx.x;
    int f = threadIdx.x;
    int deg = g_cnt[n];
    int start = g_rowstart[n];
    __shared__ int es[128];
    float acc = 0.0f;
    for (int base = 0; base < deg; base += 128) {
        int m = min(128, deg - base);
        __syncthreads();
        if (f < m) es[f] = g_inlist[start + base + f];
        __syncthreads();
        for (int e = 0; e < m; e++) acc += g_pq[(size_t)es[e] * 256 + f];
    }
    float h2 = acc * g_dinv[n] + g_pq[(size_t)n * 256 + 128 + f];
    int g = ld_idx(batch, n, g_b64);
    atomicAdd(&g_gsum[g * 128 + f], h2);
    if (f == 0) atomicAdd(&g_gcnt[g], 1);
}

// ---------------- layernorm over feature dim per graph ----------------------
__global__ void k_ln(const float* __restrict__ gamma,
                     const float* __restrict__ beta,
                     float* __restrict__ out) {
    int g = blockIdx.x;
    int f = threadIdx.x;
    __shared__ float sh[128];
    float v = g_gsum[g * 128 + f] / fmaxf((float)g_gcnt[g], 1.0f);

    sh[f] = v;
    __syncthreads();
    for (int o = 64; o; o >>= 1) {
        if (f < o) sh[f] += sh[f + o];
        __syncthreads();
    }
    float mean = sh[0] * (1.0f / 128.0f);
    __syncthreads();

    float d = v - mean;
    sh[f] = d * d;
    __syncthreads();
    for (int o = 64; o; o >>= 1) {
        if (f < o) sh[f] += sh[f + o];
        __syncthreads();
    }
    float var = sh[0] * (1.0f / 128.0f);

    out[g * 128 + f] = d * rsqrtf(var + 1e-5f) * gamma[f] + beta[f];
}

// ---------------- launch -----------------------------------------------------
extern "C" void kernel_launch(void* const* d_in, const int* in_sizes, int n_in,
                              void* d_out, int out_size) {
    const float* x     = (const float*)d_in[0];
    const void*  ei    = d_in[1];
    const void*  batch = d_in[2];
    const float* Wl0 = (const float*)d_in[3];
    const float* b0  = (const float*)d_in[4];
    const float* Wr0 = (const float*)d_in[5];
    const float* Wl1 = (const float*)d_in[6];
    const float* b1  = (const float*)d_in[7];
    const float* Wr1 = (const float*)d_in[8];
    const float* Wl2 = (const float*)d_in[9];
    const float* b2  = (const float*)d_in[10];
    const float* Wr2 = (const float*)d_in[11];
    const float* gamma = (const float*)d_in[12];
    const float* beta  = (const float*)d_in[13];
    float* out = (float*)d_out;

    cudaFuncSetAttribute(k_hgemm, cudaFuncAttributeMaxDynamicSharedMemorySize,
                         SMEM_BYTES);

    // setup: dtype detect, pointer table, zeroing, weight split
    k_setup<<<768, 256>>>((const int*)ei, (const int*)batch, Wl1, Wr1, Wl2, Wr2);

    // CSR build
    k_count<<<512, 256>>>(ei);
    k_scan1<<<NB_SCAN, SCAN_B>>>();
    k_scan3<<<NB_SCAN, SCAN_B>>>();
    k_scatter<<<512, 256>>>(ei);

    // layer 0 (rank-1) -> h0 hi plane + (agg0, x) scalars
    k_layer0<<<(N_NODES * 32 + 255) / 256, 256>>>(x, Wl0, b0, Wr0);

    // layer 1: scalar-recompute gather then h1 = relu([a1|h0] @ [Wl1;Wr1] + b1)
    k_gather1<<<N_NODES, 128>>>(Wl0, b0, Wr0);
    {
        dim3 grid(2, (N_NODES + 127) / 128);
        k_hgemm<<<grid, 256, SMEM_BYTES>>>(1, 256, 0, 256, 4, b1, 0, 1, 1, 2,
                                           N_NODES, 256);
    }

    // layer 2 fused: g_pq = h1 @ [Wl2 | Wr2], bias b2 on cols >= 128
    {
        dim3 grid(2, (N_NODES + 127) / 128);
        k_hgemm<<<grid, 256, SMEM_BYTES>>>(2, 256, -1, 0, 6, b2, 128, 0, 0, 0,
                                           N_NODES, 256);
    }

    // aggregate p, add q, pool into graph sums
    k_final<<<N_NODES, 128>>>(batch);

    // layernorm
    k_ln<<<N_GRAPHS, 128>>>(gamma, beta, out);
}

// round 14
// speedup vs baseline: 1.5329x; 1.1778x over previous
#include <cuda_runtime.h>
#include <cuda_fp16.h>
#include <cstdint>
#include <math.h>

#define N_NODES  50000
#define N_EDGES  800000
#define N_GRAPHS 64
#define SCAN_B   1024
#define NB_SCAN  ((N_NODES + SCAN_B - 1) / SCAN_B)   // 49
#define PA 40                    // smem pitch in halves
#define PLANE (128 * PA)         // halves per plane tile
#define SS (2 * PLANE)           // halves per stage (A hi | B hi)
#define SMEM_BYTES (2 * SS * 2)  // 2 stages, 2 bytes/half = 40960

// ---------------- scratch (device globals; no allocation allowed) ----------
__device__ __align__(16) __half g_h0[N_NODES * 256];
__device__ __align__(16) __half g_a1[N_NODES * 256];
__device__ __align__(16) __half g_h1[N_NODES * 256];
__device__ __align__(16) __half g_pq[N_NODES * 256];    // fp16: p cols 0-127, q cols 128-255
__device__ __align__(16) __half g_W1[256 * 512];        // [n][k], k<256: Wl1, k>=256: Wr1
__device__ __align__(16) __half g_W2[256 * 256];        // [n][k], n<128: Wl2, n>=128: Wr2
__device__ __align__(8)  float2 g_ax[N_NODES];          // (agg0, x) per node
__device__ float g_dinv[N_NODES];
__device__ int   g_cnt[N_NODES];
__device__ int   g_rowstart[N_NODES];
__device__ int   g_cursor[N_NODES];
__device__ int   g_inlist[N_EDGES];
__device__ float g_gsum[N_GRAPHS * 128];
__device__ int   g_gcnt[N_GRAPHS];
__device__ int   g_bsums[64];

__device__ int     g_ei64;
__device__ int     g_b64;
__device__ __half* g_hp[6];   // 0:h0 1:a1 2:h1 3:pq 4:W1 5:W2

__device__ __forceinline__ int ld_idx(const void* p, long long i, int is64) {
    return is64 ? (int)((const long long*)p)[i] : ((const int*)p)[i];
}

__device__ __forceinline__ unsigned smem_u32(const void* p) {
    return (unsigned)__cvta_generic_to_shared(p);
}

__device__ __forceinline__ void cp16(unsigned dst, const void* src) {
    asm volatile("cp.async.cg.shared.global [%0], [%1], 16;\n" :: "r"(dst), "l"(src));
}

// ---------------- setup: dtype detect + pointers + zero + weight convert ----
__global__ void k_setup(const int* ei_w, const int* b_w,
                        const float* __restrict__ Wl1, const float* __restrict__ Wr1,
                        const float* __restrict__ Wl2, const float* __restrict__ Wr2) {
    int i = blockIdx.x * blockDim.x + threadIdx.x;
    if (i == 0) {
        int a = 1;
        for (int k = 0; k < 64; k++) if (ei_w[2 * k + 1] != 0) { a = 0; break; }
        g_ei64 = a;
        a = 1;
        for (int k = 0; k < 64; k++) if (b_w[49001 + 2 * k] != 0) { a = 0; break; }
        g_b64 = a;

        g_hp[0] = g_h0; g_hp[1] = g_a1; g_hp[2] = g_h1;
        g_hp[3] = g_pq; g_hp[4] = g_W1; g_hp[5] = g_W2;
    }
    if (i < 131072) {                       // W1: [n=256][k=512]
        int n = i >> 9, k = i & 511;
        float w = (k < 256) ? Wl1[k * 256 + n] : Wr1[(k - 256) * 256 + n];
        g_W1[i] = __float2half_rn(w);
    } else if (i < 196608) {                // W2: [n=256][k=256]
        int j = i - 131072;
        int n = j >> 8, k = j & 255;
        float w = (n < 128) ? Wl2[k * 128 + n] : Wr2[k * 128 + (n - 128)];
        g_W2[j] = __float2half_rn(w);
    }
    int stride = gridDim.x * blockDim.x;
    for (int j = i; j < N_NODES; j += stride) g_cnt[j] = 0;
    for (int j = i; j < N_GRAPHS * 128; j += stride) g_gsum[j] = 0.0f;
    for (int j = i; j < N_GRAPHS; j += stride) g_gcnt[j] = 0;
}

// ---------------- CSR build -------------------------------------------------
__global__ void k_count(const void* __restrict__ ei) {
    int is64 = g_ei64;
    int i = blockIdx.x * blockDim.x + threadIdx.x;
    int stride = gridDim.x * blockDim.x;
    for (int e = i; e < N_EDGES; e += stride) {
        int d = ld_idx(ei, (long long)N_EDGES + e, is64);
        atomicAdd(&g_cnt[d], 1);
    }
}

__global__ void k_scan1() {
    __shared__ int s[SCAN_B];
    int i = blockIdx.x * SCAN_B + threadIdx.x;
    int v = (i < N_NODES) ? g_cnt[i] : 0;
    s[threadIdx.x] = v;
    __syncthreads();
    for (int off = 1; off < SCAN_B; off <<= 1) {
        int t = (threadIdx.x >= off) ? s[threadIdx.x - off] : 0;
        __syncthreads();
        s[threadIdx.x] += t;
        __syncthreads();
    }
    if (i < N_NODES) g_rowstart[i] = s[threadIdx.x];
    if (threadIdx.x == SCAN_B - 1) g_bsums[blockIdx.x] = s[SCAN_B - 1];
}

// scan3 also does scan2's job: per-block prefix over the 49 block sums.
__global__ void k_scan3() {
    __shared__ int boff;
    int b = blockIdx.x;
    if (threadIdx.x == 0) {
        int run = 0;
        for (int j = 0; j < b; j++) run += g_bsums[j];
        boff = run;
    }
    __syncthreads();
    int i = b * SCAN_B + threadIdx.x;
    if (i >= N_NODES) return;
    int incl = g_rowstart[i];
    int excl = incl - g_cnt[i] + boff;
    g_rowstart[i] = excl;
    g_cursor[i] = excl;
}

__global__ void k_scatter(const void* __restrict__ ei) {
    int is64 = g_ei64;
    int i = blockIdx.x * blockDim.x + threadIdx.x;
    int stride = gridDim.x * blockDim.x;
    for (int e = i; e < N_EDGES; e += stride) {
        int s = ld_idx(ei, e, is64);
        int d = ld_idx(ei, (long long)N_EDGES + e, is64);
        int pos = atomicAdd(&g_cursor[d], 1);
        g_inlist[pos] = s;
    }
}

// ---------------- layer 0 (rank-1): warp per node ---------------------------
__global__ void k_layer0(const float* __restrict__ x,
                         const float* __restrict__ Wl0,
                         const float* __restrict__ b0,
                         const float* __restrict__ Wr0) {
    int wid = (blockIdx.x * blockDim.x + threadIdx.x) >> 5;
    int lane = threadIdx.x & 31;
    if (wid >= N_NODES) return;
    int deg = g_cnt[wid];
    int start = g_rowstart[wid];
    float s = 0.0f;
    for (int i = lane; i < deg; i += 32) s += x[g_inlist[start + i]];
    #pragma unroll
    for (int o = 16; o; o >>= 1) s += __shfl_xor_sync(0xFFFFFFFFu, s, o);
    float dinv = 1.0f / fmaxf((float)deg, 1.0f);
    float agg = s * dinv;
    float xv = x[wid];
    if (lane == 0) {
        g_dinv[wid] = dinv;
        g_ax[wid] = make_float2(agg, xv);
    }
    #pragma unroll
    for (int i = 0; i < 8; i++) {
        int f = i * 32 + lane;
        float v = fmaf(agg, Wl0[f], fmaf(xv, Wr0[f], b0[f]));
        g_h0[wid * 256 + f] = __float2half_rn(fmaxf(v, 0.0f));
    }
}

// ---------------- gather1: block per node, recompute h0 from scalars --------
__global__ void k_gather1(const float* __restrict__ Wl0,
                          const float* __restrict__ b0,
                          const float* __restrict__ Wr0) {
    int n = blockIdx.x;
    int f2 = threadIdx.x;                 // features 2*f2, 2*f2+1
    int deg = g_cnt[n];
    int start = g_rowstart[n];

    float wl0 = Wl0[2 * f2], wl1 = Wl0[2 * f2 + 1];
    float wr0 = Wr0[2 * f2], wr1 = Wr0[2 * f2 + 1];
    float bb0 = b0[2 * f2],  bb1 = b0[2 * f2 + 1];

    __shared__ float2 es[128];
    float a0 = 0.0f, a1 = 0.0f;
    for (int base = 0; base < deg; base += 128) {
        int m = min(128, deg - base);
        __syncthreads();
        if (f2 < m) es[f2] = g_ax[g_inlist[start + base + f2]];
        __syncthreads();
        for (int e = 0; e < m; e++) {
            float2 ax = es[e];
            a0 += fmaxf(fmaf(ax.x, wl0, fmaf(ax.y, wr0, bb0)), 0.0f);
            a1 += fmaxf(fmaf(ax.x, wl1, fmaf(ax.y, wr1, bb1)), 0.0f);
        }
    }
    float dinv = g_dinv[n];
    *(__half2*)&g_a1[(size_t)n * 256 + 2 * f2] =
        __halves2half2(__float2half_rn(a0 * dinv), __float2half_rn(a1 * dinv));
}

// ---------------- pure fp16 HMMA GEMM: C = act(A @ B^T + bias), fp16 out ----
__device__ __forceinline__ void mma16816(float* d, const unsigned* a, const unsigned* b) {
    asm volatile(
        "mma.sync.aligned.m16n8k16.row.col.f32.f16.f16.f32 "
        "{%0,%1,%2,%3}, {%4,%5,%6,%7}, {%8,%9}, {%0,%1,%2,%3};\n"
        : "+f"(d[0]), "+f"(d[1]), "+f"(d[2]), "+f"(d[3])
        : "r"(a[0]), "r"(a[1]), "r"(a[2]), "r"(a[3]), "r"(b[0]), "r"(b[1]));
}

__global__ void __launch_bounds__(256, 2)
k_hgemm(int sA0, int K0, int sA1, int K1, int sB,
        const float* __restrict__ bias, int bias_from, int relu,
        int sOut, int nrows, int ncols) {
    const __half* A0 = g_hp[sA0];
    const __half* A1 = (sA1 >= 0) ? g_hp[sA1] : (const __half*)0;
    const __half* B = g_hp[sB];
    __half* O = g_hp[sOut];

    extern __shared__ __half sm[];   // [2 stages][A | B]

    int tid = threadIdx.x;
    int lane = tid & 31;
    int wid = tid >> 5;
    int wm = wid & 1;
    int wn = wid >> 1;
    int g = lane >> 2;
    int t2 = (lane & 3) * 2;
    int rowBase = blockIdx.y * 128;
    int colBase = blockIdx.x * 128;
    int K = K0 + K1;
    int NIT = K >> 5;

    int r_[2], kc_[2];
    #pragma unroll
    for (int it = 0; it < 2; it++) {
        int ch = tid + it * 256;
        r_[it] = ch >> 2;
        kc_[it] = (ch & 3) * 8;
    }

    float c[4][4][4];
    #pragma unroll
    for (int i = 0; i < 4; i++)
        #pragma unroll
        for (int j = 0; j < 4; j++)
            #pragma unroll
            for (int q = 0; q < 4; q++) c[i][j][q] = 0.0f;

    auto issue = [&](int iter) {
        int st = iter & 1;
        int k0 = iter << 5;
        __half* base = sm + st * SS;
        #pragma unroll
        for (int it = 0; it < 2; it++) {
            int r = r_[it], kc = kc_[it];
            int row = rowBase + r;
            int kk = k0 + kc;
            unsigned dh = smem_u32(&base[r * PA + kc]);
            if (row < nrows) {
                const __half* ph = (kk < K0)
                    ? (A0 + (size_t)row * K0 + kk)
                    : (A1 + (size_t)row * K1 + (kk - K0));
                cp16(dh, ph);
            } else {
                *(uint4*)&base[r * PA + kc] = make_uint4(0, 0, 0, 0);
            }
        }
        #pragma unroll
        for (int it = 0; it < 2; it++) {
            int n = r_[it], kc = kc_[it];
            int col = colBase + n;
            int kk = k0 + kc;
            cp16(smem_u32(&base[PLANE + n * PA + kc]), B + (size_t)col * K + kk);
        }
        asm volatile("cp.async.commit_group;\n" ::: "memory");
    };

    issue(0);

    for (int iter = 0; iter < NIT; iter++) {
        if (iter + 1 < NIT) {
            issue(iter + 1);
            asm volatile("cp.async.wait_group 1;\n" ::: "memory");
        } else {
            asm volatile("cp.async.wait_group 0;\n" ::: "memory");
        }
        __syncthreads();

        const __half* As = sm + (iter & 1) * SS;
        const __half* Bs = As + PLANE;

        #pragma unroll
        for (int ks = 0; ks < 2; ks++) {
            int kb = ks * 16;
            unsigned af[4][4], bf[4][2];
            #pragma unroll
            for (int mt = 0; mt < 4; mt++) {
                int rb = wm * 64 + mt * 16;
                af[mt][0] = *(const unsigned*)&As[(rb + g) * PA + kb + t2];
                af[mt][1] = *(const unsigned*)&As[(rb + g + 8) * PA + kb + t2];
                af[mt][2] = *(const unsigned*)&As[(rb + g) * PA + kb + t2 + 8];
                af[mt][3] = *(const unsigned*)&As[(rb + g + 8) * PA + kb + t2 + 8];
            }
            #pragma unroll
            for (int nt = 0; nt < 4; nt++) {
                int nb = wn * 32 + nt * 8 + g;
                bf[nt][0] = *(const unsigned*)&Bs[nb * PA + kb + t2];
                bf[nt][1] = *(const unsigned*)&Bs[nb * PA + kb + t2 + 8];
            }
            #pragma unroll
            for (int mt = 0; mt < 4; mt++)
                #pragma unroll
                for (int nt = 0; nt < 4; nt++)
                    mma16816(c[mt][nt], af[mt], bf[nt]);
        }
        __syncthreads();
    }

    #pragma unroll
    for (int mt = 0; mt < 4; mt++) {
        #pragma unroll
        for (int nt = 0; nt < 4; nt++) {
            int r0 = rowBase + wm * 64 + mt * 16 + g;
            int cc = colBase + wn * 32 + nt * 8 + t2;
            float bv0 = 0.0f, bv1 = 0.0f;
            if (bias) {
                if (cc >= bias_from)     bv0 = bias[cc - bias_from];
                if (cc + 1 >= bias_from) bv1 = bias[cc + 1 - bias_from];
            }
            #pragma unroll
            for (int half_ : {0, 1}) {
                int row = r0 + half_ * 8;
                if (row >= nrows) continue;
                float v0 = c[mt][nt][half_ * 2 + 0] + bv0;
                float v1 = c[mt][nt][half_ * 2 + 1] + bv1;
                if (relu) { v0 = fmaxf(v0, 0.0f); v1 = fmaxf(v1, 0.0f); }
                *(__half2*)&O[(size_t)row * ncols + cc] =
                    __halves2half2(__float2half_rn(v0), __float2half_rn(v1));
            }
        }
    }
}

// ---------------- final: block per node; fp16 p/q reads ---------------------
__global__ void k_final(const void* __restrict__ batch) {
    int n = blockIdx.x;
    int f = threadIdx.x;
    int deg = g_cnt[n];
    int start = g_rowstart[n];
    __shared__ int es[128];
    float acc = 0.0f;
    for (int base = 0; base < deg; base += 128) {
        int m = min(128, deg - base);
        __syncthreads();
        if (f < m) es[f] = g_inlist[start + base + f];
        __syncthreads();
        for (int e = 0; e < m; e++)
            acc += __half2float(g_pq[(size_t)es[e] * 256 + f]);
    }
    float h2 = acc * g_dinv[n] + __half2float(g_pq[(size_t)n * 256 + 128 + f]);
    int g = ld_idx(batch, n, g_b64);
    atomicAdd(&g_gsum[g * 128 + f], h2);
    if (f == 0) atomicAdd(&g_gcnt[g], 1);
}

// ---------------- layernorm over feature dim per graph ----------------------
__global__ void k_ln(const float* __restrict__ gamma,
                     const float* __restrict__ beta,
                     float* __restrict__ out) {
    int g = blockIdx.x;
    int f = threadIdx.x;
    __shared__ float sh[128];
    float v = g_gsum[g * 128 + f] / fmaxf((float)g_gcnt[g], 1.0f);

    sh[f] = v;
    __syncthreads();
    for (int o = 64; o; o >>= 1) {
        if (f < o) sh[f] += sh[f + o];
        __syncthreads();
    }
    float mean = sh[0] * (1.0f / 128.0f);
    __syncthreads();

    float d = v - mean;
    sh[f] = d * d;
    __syncthreads();
    for (int o = 64; o; o >>= 1) {
        if (f < o) sh[f] += sh[f + o];
        __syncthreads();
    }
    float var = sh[0] * (1.0f / 128.0f);

    out[g * 128 + f] = d * rsqrtf(var + 1e-5f) * gamma[f] + beta[f];
}

// ---------------- launch -----------------------------------------------------
extern "C" void kernel_launch(void* const* d_in, const int* in_sizes, int n_in,
                              void* d_out, int out_size) {
    const float* x     = (const float*)d_in[0];
    const void*  ei    = d_in[1];
    const void*  batch = d_in[2];
    const float* Wl0 = (const float*)d_in[3];
    const float* b0  = (const float*)d_in[4];
    const float* Wr0 = (const float*)d_in[5];
    const float* Wl1 = (const float*)d_in[6];
    const float* b1  = (const float*)d_in[7];
    const float* Wr1 = (const float*)d_in[8];
    const float* Wl2 = (const float*)d_in[9];
    const float* b2  = (const float*)d_in[10];
    const float* Wr2 = (const float*)d_in[11];
    const float* gamma = (const float*)d_in[12];
    const float* beta  = (const float*)d_in[13];
    float* out = (float*)d_out;

    cudaFuncSetAttribute(k_hgemm, cudaFuncAttributeMaxDynamicSharedMemorySize,
                         SMEM_BYTES);

    // setup: dtype detect, pointer table, zeroing, weight convert
    k_setup<<<768, 256>>>((const int*)ei, (const int*)batch, Wl1, Wr1, Wl2, Wr2);

    // CSR build
    k_count<<<512, 256>>>(ei);
    k_scan1<<<NB_SCAN, SCAN_B>>>();
    k_scan3<<<NB_SCAN, SCAN_B>>>();
    k_scatter<<<512, 256>>>(ei);

    // layer 0 (rank-1) -> h0 fp16 + (agg0, x) scalars
    k_layer0<<<(N_NODES * 32 + 255) / 256, 256>>>(x, Wl0, b0, Wr0);

    // layer 1: scalar-recompute gather then h1 = relu([a1|h0] @ [Wl1;Wr1] + b1)
    k_gather1<<<N_NODES, 128>>>(Wl0, b0, Wr0);
    {
        dim3 grid(2, (N_NODES + 127) / 128);
        k_hgemm<<<grid, 256, SMEM_BYTES>>>(1, 256, 0, 256, 4, b1, 0, 1, 2,
                                           N_NODES, 256);
    }

    // layer 2 fused: g_pq = h1 @ [Wl2 | Wr2], bias b2 on cols >= 128
    {
        dim3 grid(2, (N_NODES + 127) / 128);
        k_hgemm<<<grid, 256, SMEM_BYTES>>>(2, 256, -1, 0, 5, b2, 128, 0, 3,
                                           N_NODES, 256);
    }

    // aggregate p (fp16 reads), add q, pool into graph sums
    k_final<<<N_NODES, 128>>>(batch);

    // layernorm
    k_ln<<<N_GRAPHS, 128>>>(gamma, beta, out);
}

// round 15
// speedup vs baseline: 1.5852x; 1.0341x over previous
#include <cuda_runtime.h>
#include <cuda_fp16.h>
#include <cstdint>
#include <math.h>

#define N_NODES  50000
#define N_EDGES  800000
#define N_GRAPHS 64
#define SCAN_B   1024
#define NB_SCAN  ((N_NODES + SCAN_B - 1) / SCAN_B)   // 49
#define PA 40                    // smem pitch in halves
#define PLANE (128 * PA)         // halves per plane tile
#define SS (2 * PLANE)           // halves per stage (A | B)
#define SMEM_BYTES (2 * SS * 2)  // 2 stages, 2 bytes/half = 40960

// ---------------- scratch (device globals; no allocation allowed) ----------
__device__ __align__(16) __half g_h0[N_NODES * 256];
__device__ __align__(16) __half g_a1[N_NODES * 256];
__device__ __align__(16) __half g_h1[N_NODES * 256];
__device__ __align__(16) __half g_pq[N_NODES * 256];    // fp16: p cols 0-127, q cols 128-255
__device__ __align__(16) __half g_W1[256 * 512];        // [n][k], k<256: Wl1, k>=256: Wr1
__device__ __align__(16) __half g_W2[256 * 256];        // [n][k], n<128: Wl2, n>=128: Wr2
__device__ __align__(8)  float2 g_ax[N_NODES];          // (agg0, x) per node
__device__ float g_dinv[N_NODES];
__device__ int   g_cnt[N_NODES];
__device__ int   g_rowstart[N_NODES];
__device__ int   g_cursor[N_NODES];
__device__ int   g_inlist[N_EDGES];
__device__ float g_gsum[N_GRAPHS * 128];
__device__ int   g_gcnt[N_GRAPHS];
__device__ int   g_bsums[64];

__device__ int     g_ei64;
__device__ int     g_b64;
__device__ __half* g_hp[6];   // 0:h0 1:a1 2:h1 3:pq 4:W1 5:W2

__device__ __forceinline__ int ld_idx(const void* p, long long i, int is64) {
    return is64 ? (int)((const long long*)p)[i] : ((const int*)p)[i];
}

__device__ __forceinline__ unsigned smem_u32(const void* p) {
    return (unsigned)__cvta_generic_to_shared(p);
}

__device__ __forceinline__ void cp16(unsigned dst, const void* src) {
    asm volatile("cp.async.cg.shared.global [%0], [%1], 16;\n" :: "r"(dst), "l"(src));
}

__device__ __forceinline__ void ldsm_x4(unsigned* r, unsigned addr) {
    asm volatile(
        "ldmatrix.sync.aligned.m8n8.x4.shared.b16 {%0, %1, %2, %3}, [%4];"
        : "=r"(r[0]), "=r"(r[1]), "=r"(r[2]), "=r"(r[3]) : "r"(addr));
}

// ---------------- setup: dtype detect + pointers + zero + weight convert ----
__global__ void k_setup(const int* ei_w, const int* b_w,
                        const float* __restrict__ Wl1, const float* __restrict__ Wr1,
                        const float* __restrict__ Wl2, const float* __restrict__ Wr2) {
    int i = blockIdx.x * blockDim.x + threadIdx.x;
    if (i == 0) {
        int a = 1;
        for (int k = 0; k < 64; k++) if (ei_w[2 * k + 1] != 0) { a = 0; break; }
        g_ei64 = a;
        a = 1;
        for (int k = 0; k < 64; k++) if (b_w[49001 + 2 * k] != 0) { a = 0; break; }
        g_b64 = a;

        g_hp[0] = g_h0; g_hp[1] = g_a1; g_hp[2] = g_h1;
        g_hp[3] = g_pq; g_hp[4] = g_W1; g_hp[5] = g_W2;
    }
    if (i < 131072) {                       // W1: [n=256][k=512]
        int n = i >> 9, k = i & 511;
        float w = (k < 256) ? Wl1[k * 256 + n] : Wr1[(k - 256) * 256 + n];
        g_W1[i] = __float2half_rn(w);
    } else if (i < 196608) {                // W2: [n=256][k=256]
        int j = i - 131072;
        int n = j >> 8, k = j & 255;
        float w = (n < 128) ? Wl2[k * 128 + n] : Wr2[k * 128 + (n - 128)];
        g_W2[j] = __float2half_rn(w);
    }
    int stride = gridDim.x * blockDim.x;
    for (int j = i; j < N_NODES; j += stride) g_cnt[j] = 0;
    for (int j = i; j < N_GRAPHS * 128; j += stride) g_gsum[j] = 0.0f;
    for (int j = i; j < N_GRAPHS; j += stride) g_gcnt[j] = 0;
}

// ---------------- CSR build -------------------------------------------------
__global__ void k_count(const void* __restrict__ ei) {
    int is64 = g_ei64;
    int i = blockIdx.x * blockDim.x + threadIdx.x;
    int stride = gridDim.x * blockDim.x;
    for (int e = i; e < N_EDGES; e += stride) {
        int d = ld_idx(ei, (long long)N_EDGES + e, is64);
        atomicAdd(&g_cnt[d], 1);
    }
}

__global__ void k_scan1() {
    __shared__ int s[SCAN_B];
    int i = blockIdx.x * SCAN_B + threadIdx.x;
    int v = (i < N_NODES) ? g_cnt[i] : 0;
    s[threadIdx.x] = v;
    __syncthreads();
    for (int off = 1; off < SCAN_B; off <<= 1) {
        int t = (threadIdx.x >= off) ? s[threadIdx.x - off] : 0;
        __syncthreads();
        s[threadIdx.x] += t;
        __syncthreads();
    }
    if (i < N_NODES) g_rowstart[i] = s[threadIdx.x];
    if (threadIdx.x == SCAN_B - 1) g_bsums[blockIdx.x] = s[SCAN_B - 1];
}

// scan3 also does scan2's job: per-block prefix over the 49 block sums.
__global__ void k_scan3() {
    __shared__ int boff;
    int b = blockIdx.x;
    if (threadIdx.x == 0) {
        int run = 0;
        for (int j = 0; j < b; j++) run += g_bsums[j];
        boff = run;
    }
    __syncthreads();
    int i = b * SCAN_B + threadIdx.x;
    if (i >= N_NODES) return;
    int incl = g_rowstart[i];
    int excl = incl - g_cnt[i] + boff;
    g_rowstart[i] = excl;
    g_cursor[i] = excl;
}

__global__ void k_scatter(const void* __restrict__ ei) {
    int is64 = g_ei64;
    int i = blockIdx.x * blockDim.x + threadIdx.x;
    int stride = gridDim.x * blockDim.x;
    for (int e = i; e < N_EDGES; e += stride) {
        int s = ld_idx(ei, e, is64);
        int d = ld_idx(ei, (long long)N_EDGES + e, is64);
        int pos = atomicAdd(&g_cursor[d], 1);
        g_inlist[pos] = s;
    }
}

// ---------------- layer 0 (rank-1): warp per node ---------------------------
__global__ void k_layer0(const float* __restrict__ x,
                         const float* __restrict__ Wl0,
                         const float* __restrict__ b0,
                         const float* __restrict__ Wr0) {
    int wid = (blockIdx.x * blockDim.x + threadIdx.x) >> 5;
    int lane = threadIdx.x & 31;
    if (wid >= N_NODES) return;
    int deg = g_cnt[wid];
    int start = g_rowstart[wid];
    float s = 0.0f;
    for (int i = lane; i < deg; i += 32) s += x[g_inlist[start + i]];
    #pragma unroll
    for (int o = 16; o; o >>= 1) s += __shfl_xor_sync(0xFFFFFFFFu, s, o);
    float dinv = 1.0f / fmaxf((float)deg, 1.0f);
    float agg = s * dinv;
    float xv = x[wid];
    if (lane == 0) {
        g_dinv[wid] = dinv;
        g_ax[wid] = make_float2(agg, xv);
    }
    #pragma unroll
    for (int i = 0; i < 8; i++) {
        int f = i * 32 + lane;
        float v = fmaf(agg, Wl0[f], fmaf(xv, Wr0[f], b0[f]));
        g_h0[wid * 256 + f] = __float2half_rn(fmaxf(v, 0.0f));
    }
}

// ---------------- gather1: block per node, recompute h0 from scalars --------
__global__ void k_gather1(const float* __restrict__ Wl0,
                          const float* __restrict__ b0,
                          const float* __restrict__ Wr0) {
    int n = blockIdx.x;
    int f2 = threadIdx.x;                 // features 2*f2, 2*f2+1
    int deg = g_cnt[n];
    int start = g_rowstart[n];

    float wl0 = Wl0[2 * f2], wl1 = Wl0[2 * f2 + 1];
    float wr0 = Wr0[2 * f2], wr1 = Wr0[2 * f2 + 1];
    float bb0 = b0[2 * f2],  bb1 = b0[2 * f2 + 1];

    __shared__ float2 es[128];
    float a0 = 0.0f, a1 = 0.0f;
    for (int base = 0; base < deg; base += 128) {
        int m = min(128, deg - base);
        __syncthreads();
        if (f2 < m) es[f2] = g_ax[g_inlist[start + base + f2]];
        __syncthreads();
        for (int e = 0; e < m; e++) {
            float2 ax = es[e];
            a0 += fmaxf(fmaf(ax.x, wl0, fmaf(ax.y, wr0, bb0)), 0.0f);
            a1 += fmaxf(fmaf(ax.x, wl1, fmaf(ax.y, wr1, bb1)), 0.0f);
        }
    }
    float dinv = g_dinv[n];
    *(__half2*)&g_a1[(size_t)n * 256 + 2 * f2] =
        __halves2half2(__float2half_rn(a0 * dinv), __float2half_rn(a1 * dinv));
}

// ---------------- pure fp16 HMMA GEMM with ldmatrix frag loads --------------
__device__ __forceinline__ void mma16816(float* d, const unsigned* a, const unsigned* b) {
    asm volatile(
        "mma.sync.aligned.m16n8k16.row.col.f32.f16.f16.f32 "
        "{%0,%1,%2,%3}, {%4,%5,%6,%7}, {%8,%9}, {%0,%1,%2,%3};\n"
        : "+f"(d[0]), "+f"(d[1]), "+f"(d[2]), "+f"(d[3])
        : "r"(a[0]), "r"(a[1]), "r"(a[2]), "r"(a[3]), "r"(b[0]), "r"(b[1]));
}

__global__ void __launch_bounds__(256, 2)
k_hgemm(int sA0, int K0, int sA1, int K1, int sB,
        const float* __restrict__ bias, int bias_from, int relu,
        int sOut, int nrows, int ncols) {
    const __half* A0 = g_hp[sA0];
    const __half* A1 = (sA1 >= 0) ? g_hp[sA1] : (const __half*)0;
    const __half* B = g_hp[sB];
    __half* O = g_hp[sOut];

    extern __shared__ __half sm[];   // [2 stages][A | B]
    unsigned sm_u32 = smem_u32(sm);

    int tid = threadIdx.x;
    int lane = tid & 31;
    int wid = tid >> 5;
    int wm = wid & 1;
    int wn = wid >> 1;
    int g = lane >> 2;
    int t2 = (lane & 3) * 2;
    int rowBase = blockIdx.y * 128;
    int colBase = blockIdx.x * 128;
    int K = K0 + K1;
    int NIT = K >> 5;

    // ldmatrix per-lane source coordinates
    // A x4: lanes 0-15 -> rows rb+0..15 (k+0); lanes 16-31 -> same rows, k+8
    int a_row = (lane & 15);
    int a_koff = (lane >> 4) << 3;
    // B x4 (two n-tiles): lanes 0-7 rows nb..nb+7 k+0; 8-15 same rows k+8;
    //                     16-23 rows nb+8..15 k+0; 24-31 same k+8
    int b_row = (lane & 7) + ((lane >> 4) << 3);
    int b_koff = ((lane >> 3) & 1) << 3;

    int r_[2], kc_[2];
    #pragma unroll
    for (int it = 0; it < 2; it++) {
        int ch = tid + it * 256;
        r_[it] = ch >> 2;
        kc_[it] = (ch & 3) * 8;
    }

    float c[4][4][4];
    #pragma unroll
    for (int i = 0; i < 4; i++)
        #pragma unroll
        for (int j = 0; j < 4; j++)
            #pragma unroll
            for (int q = 0; q < 4; q++) c[i][j][q] = 0.0f;

    auto issue = [&](int iter) {
        int st = iter & 1;
        int k0 = iter << 5;
        __half* base = sm + st * SS;
        #pragma unroll
        for (int it = 0; it < 2; it++) {
            int r = r_[it], kc = kc_[it];
            int row = rowBase + r;
            int kk = k0 + kc;
            unsigned dh = smem_u32(&base[r * PA + kc]);
            if (row < nrows) {
                const __half* ph = (kk < K0)
                    ? (A0 + (size_t)row * K0 + kk)
                    : (A1 + (size_t)row * K1 + (kk - K0));
                cp16(dh, ph);
            } else {
                *(uint4*)&base[r * PA + kc] = make_uint4(0, 0, 0, 0);
            }
        }
        #pragma unroll
        for (int it = 0; it < 2; it++) {
            int n = r_[it], kc = kc_[it];
            int col = colBase + n;
            int kk = k0 + kc;
            cp16(smem_u32(&base[PLANE + n * PA + kc]), B + (size_t)col * K + kk);
        }
        asm volatile("cp.async.commit_group;\n" ::: "memory");
    };

    issue(0);

    for (int iter = 0; iter < NIT; iter++) {
        if (iter + 1 < NIT) {
            issue(iter + 1);
            asm volatile("cp.async.wait_group 1;\n" ::: "memory");
        } else {
            asm volatile("cp.async.wait_group 0;\n" ::: "memory");
        }
        __syncthreads();

        unsigned As_u = sm_u32 + (unsigned)((iter & 1) * SS) * 2u;
        unsigned Bs_u = As_u + (unsigned)PLANE * 2u;

        #pragma unroll
        for (int ks = 0; ks < 2; ks++) {
            int kb = ks * 16;
            unsigned af[4][4], bf[4][2];
            // A frags: one ldmatrix.x4 per 16-row m-tile
            #pragma unroll
            for (int mt = 0; mt < 4; mt++) {
                int rb = wm * 64 + mt * 16;
                unsigned addr = As_u +
                    (unsigned)(((rb + a_row) * PA) + kb + a_koff) * 2u;
                ldsm_x4(af[mt], addr);
            }
            // B frags: one ldmatrix.x4 per n-tile PAIR
            #pragma unroll
            for (int ntp = 0; ntp < 2; ntp++) {
                int nb = wn * 32 + ntp * 16;
                unsigned addr = Bs_u +
                    (unsigned)(((nb + b_row) * PA) + kb + b_koff) * 2u;
                unsigned r4[4];
                ldsm_x4(r4, addr);
                bf[ntp * 2 + 0][0] = r4[0];
                bf[ntp * 2 + 0][1] = r4[1];
                bf[ntp * 2 + 1][0] = r4[2];
                bf[ntp * 2 + 1][1] = r4[3];
            }
            #pragma unroll
            for (int mt = 0; mt < 4; mt++)
                #pragma unroll
                for (int nt = 0; nt < 4; nt++)
                    mma16816(c[mt][nt], af[mt], bf[nt]);
        }
        __syncthreads();
    }

    #pragma unroll
    for (int mt = 0; mt < 4; mt++) {
        #pragma unroll
        for (int nt = 0; nt < 4; nt++) {
            int r0 = rowBase + wm * 64 + mt * 16 + g;
            int cc = colBase + wn * 32 + nt * 8 + t2;
            float bv0 = 0.0f, bv1 = 0.0f;
            if (bias) {
                if (cc >= bias_from)     bv0 = bias[cc - bias_from];
                if (cc + 1 >= bias_from) bv1 = bias[cc + 1 - bias_from];
            }
            #pragma unroll
            for (int half_ : {0, 1}) {
                int row = r0 + half_ * 8;
                if (row >= nrows) continue;
                float v0 = c[mt][nt][half_ * 2 + 0] + bv0;
                float v1 = c[mt][nt][half_ * 2 + 1] + bv1;
                if (relu) { v0 = fmaxf(v0, 0.0f); v1 = fmaxf(v1, 0.0f); }
                *(__half2*)&O[(size_t)row * ncols + cc] =
                    __halves2half2(__float2half_rn(v0), __float2half_rn(v1));
            }
        }
    }
}

// ---------------- final: block per node; fp16 p/q reads ---------------------
__global__ void k_final(const void* __restrict__ batch) {
    int n = blockIdx.x;
    int f = threadIdx.x;
    int deg = g_cnt[n];
    int start = g_rowstart[n];
    __shared__ int es[128];
    float acc = 0.0f;
    for (int base = 0; base < deg; base += 128) {
        int m = min(128, deg - base);
        __syncthreads();
        if (f < m) es[f] = g_inlist[start + base + f];
        __syncthreads();
        for (int e = 0; e < m; e++)
            acc += __half2float(g_pq[(size_t)es[e] * 256 + f]);
    }
    float h2 = acc * g_dinv[n] + __half2float(g_pq[(size_t)n * 256 + 128 + f]);
    int g = ld_idx(batch, n, g_b64);
    atomicAdd(&g_gsum[g * 128 + f], h2);
    if (f == 0) atomicAdd(&g_gcnt[g], 1);
}

// ---------------- layernorm over feature dim per graph ----------------------
__global__ void k_ln(const float* __restrict__ gamma,
                     const float* __restrict__ beta,
                     float* __restrict__ out) {
    int g = blockIdx.x;
    int f = threadIdx.x;
    __shared__ float sh[128];
    float v = g_gsum[g * 128 + f] / fmaxf((float)g_gcnt[g], 1.0f);

    sh[f] = v;
    __syncthreads();
    for (int o = 64; o; o >>= 1) {
        if (f < o) sh[f] += sh[f + o];
        __syncthreads();
    }
    float mean = sh[0] * (1.0f / 128.0f);
    __syncthreads();

    float d = v - mean;
    sh[f] = d * d;
    __syncthreads();
    for (int o = 64; o; o >>= 1) {
        if (f < o) sh[f] += sh[f + o];
        __syncthreads();
    }
    float var = sh[0] * (1.0f / 128.0f);

    out[g * 128 + f] = d * rsqrtf(var + 1e-5f) * gamma[f] + beta[f];
}

// ---------------- launch -----------------------------------------------------
extern "C" void kernel_launch(void* const* d_in, const int* in_sizes, int n_in,
                              void* d_out, int out_size) {
    const float* x     = (const float*)d_in[0];
    const void*  ei    = d_in[1];
    const void*  batch = d_in[2];
    const float* Wl0 = (const float*)d_in[3];
    const float* b0  = (const float*)d_in[4];
    const float* Wr0 = (const float*)d_in[5];
    const float* Wl1 = (const float*)d_in[6];
    const float* b1  = (const float*)d_in[7];
    const float* Wr1 = (const float*)d_in[8];
    const float* Wl2 = (const float*)d_in[9];
    const float* b2  = (const float*)d_in[10];
    const float* Wr2 = (const float*)d_in[11];
    const float* gamma = (const float*)d_in[12];
    const float* beta  = (const float*)d_in[13];
    float* out = (float*)d_out;

    cudaFuncSetAttribute(k_hgemm, cudaFuncAttributeMaxDynamicSharedMemorySize,
                         SMEM_BYTES);

    // setup: dtype detect, pointer table, zeroing, weight convert
    k_setup<<<768, 256>>>((const int*)ei, (const int*)batch, Wl1, Wr1, Wl2, Wr2);

    // CSR build
    k_count<<<512, 256>>>(ei);
    k_scan1<<<NB_SCAN, SCAN_B>>>();
    k_scan3<<<NB_SCAN, SCAN_B>>>();
    k_scatter<<<512, 256>>>(ei);

    // layer 0 (rank-1) -> h0 fp16 + (agg0, x) scalars
    k_layer0<<<(N_NODES * 32 + 255) / 256, 256>>>(x, Wl0, b0, Wr0);

    // layer 1: scalar-recompute gather then h1 = relu([a1|h0] @ [Wl1;Wr1] + b1)
    k_gather1<<<N_NODES, 128>>>(Wl0, b0, Wr0);
    {
        dim3 grid(2, (N_NODES + 127) / 128);
        k_hgemm<<<grid, 256, SMEM_BYTES>>>(1, 256, 0, 256, 4, b1, 0, 1, 2,
                                           N_NODES, 256);
    }

    // layer 2 fused: g_pq = h1 @ [Wl2 | Wr2], bias b2 on cols >= 128
    {
        dim3 grid(2, (N_NODES + 127) / 128);
        k_hgemm<<<grid, 256, SMEM_BYTES>>>(2, 256, -1, 0, 5, b2, 128, 0, 3,
                                           N_NODES, 256);
    }

    // aggregate p (fp16 reads), add q, pool into graph sums
    k_final<<<N_NODES, 128>>>(batch);

    // layernorm
    k_ln<<<N_GRAPHS, 128>>>(gamma, beta, out);
}